// round 2
// baseline (speedup 1.0000x reference)
#include <cuda_runtime.h>
#include <math.h>
#include <stdint.h>

#define HEADS 16
#define HDIM  64
#define BATCH 2
#define TLEN  2048
#define EDIM  1024
#define MROWS (BATCH*TLEN)   // 4096

// Scratch (allocation-free rule: __device__ globals)
__device__ float g_q[MROWS*EDIM];
__device__ float g_k[MROWS*EDIM];
__device__ float g_v[MROWS*EDIM];
__device__ float g_att[MROWS*EDIM];

// ---------------------------------------------------------------------------
// TF32 helpers
// ---------------------------------------------------------------------------
__device__ __forceinline__ unsigned f2tf32(float x) {
    unsigned u;
    asm("cvt.rna.tf32.f32 %0, %1;" : "=r"(u) : "f"(x));
    return u;
}

__device__ __forceinline__ void mma8(float* c, const unsigned* a, const unsigned* b) {
    asm volatile(
        "mma.sync.aligned.m16n8k8.row.col.f32.tf32.tf32.f32 "
        "{%0,%1,%2,%3}, {%4,%5,%6,%7}, {%8,%9}, {%0,%1,%2,%3};\n"
        : "+f"(c[0]), "+f"(c[1]), "+f"(c[2]), "+f"(c[3])
        : "r"(a[0]), "r"(a[1]), "r"(a[2]), "r"(a[3]), "r"(b[0]), "r"(b[1]));
}

// ---------------------------------------------------------------------------
// 3xTF32 tensor-core GEMM: C[M,N] = A[M,K] @ B[K,N] (+ bias)
// BM=BN=128, BK=16, 256 threads (8 warps, 2x4 grid of 64x32 warp tiles).
// hi/lo split precomputed into smem as float2; double-buffered.
// ---------------------------------------------------------------------------
#define AS_STRIDE 132              // float2 units (BM + 4 pad)
#define STAGE_F2  (16 * AS_STRIDE) // 2112 float2 per operand stage
#define GEMM_SMEM (4 * STAGE_F2 * (int)sizeof(float2))  // 67584 B

__global__ __launch_bounds__(256, 1)
void gemm_tf32(const float* __restrict__ A, const float* __restrict__ B,
               const float* __restrict__ bias, float* __restrict__ C,
               int M, int N, int K)
{
    extern __shared__ float2 sm[];
    float2* As[2] = { sm,              sm + STAGE_F2 };
    float2* Bs[2] = { sm + 2*STAGE_F2, sm + 3*STAGE_F2 };

    const int tid  = threadIdx.x;
    const int lane = tid & 31;
    const int w    = tid >> 5;
    const int warpM = (w >> 2) * 64;   // 0 or 64
    const int warpN = (w & 3) * 32;    // 0,32,64,96
    const int gid  = lane >> 2;        // groupID 0..7
    const int tg   = lane & 3;         // 0..3

    const int brow = blockIdx.y * 128;
    const int bcol = blockIdx.x * 128;

    // gmem load mapping
    const int am = tid >> 1;           // A row in tile, 0..127
    const int ak = (tid & 1) * 8;      // A k offset, 0 or 8
    const int bk = tid >> 5;           // B k row, 0..7 (and +8)
    const int bn = (tid & 31) * 4;     // B col, 0..124

    const float* Ag = A + (size_t)(brow + am) * K + ak;
    const float* Bg = B + (size_t)bk * N + (bcol + bn);

    float4 ra0, ra1, rb0, rb1;
    ra0 = *(const float4*)(Ag);
    ra1 = *(const float4*)(Ag + 4);
    rb0 = *(const float4*)(Bg);
    rb1 = *(const float4*)(Bg + (size_t)8 * N);

    float acc[4][4][4];
    #pragma unroll
    for (int mt = 0; mt < 4; mt++)
        #pragma unroll
        for (int nt = 0; nt < 4; nt++)
            #pragma unroll
            for (int i = 0; i < 4; i++) acc[mt][nt][i] = 0.f;

    // store tile 0
    {
        float va[8] = {ra0.x, ra0.y, ra0.z, ra0.w, ra1.x, ra1.y, ra1.z, ra1.w};
        #pragma unroll
        for (int i = 0; i < 8; i++) {
            unsigned hi = f2tf32(va[i]);
            unsigned lo = f2tf32(va[i] - __uint_as_float(hi));
            As[0][(ak + i) * AS_STRIDE + am] =
                make_float2(__uint_as_float(hi), __uint_as_float(lo));
        }
        float vb[8] = {rb0.x, rb0.y, rb0.z, rb0.w, rb1.x, rb1.y, rb1.z, rb1.w};
        #pragma unroll
        for (int h = 0; h < 2; h++)
            #pragma unroll
            for (int i = 0; i < 4; i++) {
                float v = vb[h * 4 + i];
                unsigned hi = f2tf32(v);
                unsigned lo = f2tf32(v - __uint_as_float(hi));
                Bs[0][(bk + h * 8) * AS_STRIDE + bn + i] =
                    make_float2(__uint_as_float(hi), __uint_as_float(lo));
            }
    }
    __syncthreads();

    const int NKI = K / 16;
    for (int t = 0; t < NKI; t++) {
        int buf = t & 1;
        if (t + 1 < NKI) {
            const float* Ag2 = Ag + (t + 1) * 16;
            ra0 = *(const float4*)(Ag2);
            ra1 = *(const float4*)(Ag2 + 4);
            const float* Bg2 = Bg + (size_t)(t + 1) * 16 * N;
            rb0 = *(const float4*)(Bg2);
            rb1 = *(const float4*)(Bg2 + (size_t)8 * N);
        }

        #pragma unroll
        for (int ks = 0; ks < 2; ks++) {
            int kb = ks * 8 + tg;
            unsigned ahi[4][4], alo[4][4];
            #pragma unroll
            for (int mt = 0; mt < 4; mt++) {
                int r = warpM + mt * 16 + gid;
                float2 p0 = As[buf][kb * AS_STRIDE + r];
                float2 p1 = As[buf][kb * AS_STRIDE + r + 8];
                float2 p2 = As[buf][(kb + 4) * AS_STRIDE + r];
                float2 p3 = As[buf][(kb + 4) * AS_STRIDE + r + 8];
                ahi[mt][0] = __float_as_uint(p0.x); alo[mt][0] = __float_as_uint(p0.y);
                ahi[mt][1] = __float_as_uint(p1.x); alo[mt][1] = __float_as_uint(p1.y);
                ahi[mt][2] = __float_as_uint(p2.x); alo[mt][2] = __float_as_uint(p2.y);
                ahi[mt][3] = __float_as_uint(p3.x); alo[mt][3] = __float_as_uint(p3.y);
            }
            unsigned bhi[4][2], blo[4][2];
            #pragma unroll
            for (int nt = 0; nt < 4; nt++) {
                int n = warpN + nt * 8 + gid;
                float2 q0 = Bs[buf][kb * AS_STRIDE + n];
                float2 q1 = Bs[buf][(kb + 4) * AS_STRIDE + n];
                bhi[nt][0] = __float_as_uint(q0.x); blo[nt][0] = __float_as_uint(q0.y);
                bhi[nt][1] = __float_as_uint(q1.x); blo[nt][1] = __float_as_uint(q1.y);
            }
            #pragma unroll
            for (int mt = 0; mt < 4; mt++)
                #pragma unroll
                for (int nt = 0; nt < 4; nt++) {
                    mma8(acc[mt][nt], ahi[mt], blo[nt]);
                    mma8(acc[mt][nt], alo[mt], bhi[nt]);
                    mma8(acc[mt][nt], ahi[mt], bhi[nt]);
                }
        }

        if (t + 1 < NKI) {
            int nbuf = buf ^ 1;
            float va[8] = {ra0.x, ra0.y, ra0.z, ra0.w, ra1.x, ra1.y, ra1.z, ra1.w};
            #pragma unroll
            for (int i = 0; i < 8; i++) {
                unsigned hi = f2tf32(va[i]);
                unsigned lo = f2tf32(va[i] - __uint_as_float(hi));
                As[nbuf][(ak + i) * AS_STRIDE + am] =
                    make_float2(__uint_as_float(hi), __uint_as_float(lo));
            }
            float vb[8] = {rb0.x, rb0.y, rb0.z, rb0.w, rb1.x, rb1.y, rb1.z, rb1.w};
            #pragma unroll
            for (int h = 0; h < 2; h++)
                #pragma unroll
                for (int i = 0; i < 4; i++) {
                    float v = vb[h * 4 + i];
                    unsigned hi = f2tf32(v);
                    unsigned lo = f2tf32(v - __uint_as_float(hi));
                    Bs[nbuf][(bk + h * 8) * AS_STRIDE + bn + i] =
                        make_float2(__uint_as_float(hi), __uint_as_float(lo));
                }
            __syncthreads();
        }
    }

    // epilogue
    #pragma unroll
    for (int mt = 0; mt < 4; mt++) {
        int r0 = brow + warpM + mt * 16 + gid;
        #pragma unroll
        for (int nt = 0; nt < 4; nt++) {
            int c0 = bcol + warpN + nt * 8 + tg * 2;
            float bx = 0.f, by = 0.f;
            if (bias) { bx = bias[c0]; by = bias[c0 + 1]; }
            float2 o0 = make_float2(acc[mt][nt][0] + bx, acc[mt][nt][1] + by);
            float2 o1 = make_float2(acc[mt][nt][2] + bx, acc[mt][nt][3] + by);
            *(float2*)(&C[(size_t)r0 * N + c0])       = o0;
            *(float2*)(&C[(size_t)(r0 + 8) * N + c0]) = o1;
        }
    }
}

// ---------------------------------------------------------------------------
// Per-head LayerNorm over head dim (64). One warp per row of 64.
// ---------------------------------------------------------------------------
__global__ __launch_bounds__(256)
void head_layernorm(float* __restrict__ x, const float* __restrict__ w,
                    const float* __restrict__ b, int nrows)
{
    int warp = (blockIdx.x * blockDim.x + threadIdx.x) >> 5;
    int lane = threadIdx.x & 31;
    if (warp >= nrows) return;
    float* row = x + (size_t)warp * HDIM;
    float v0 = row[lane];
    float v1 = row[lane + 32];
    float s = v0 + v1;
    #pragma unroll
    for (int o = 16; o > 0; o >>= 1) s += __shfl_xor_sync(0xffffffffu, s, o);
    float mu = s * (1.f / 64.f);
    float d0 = v0 - mu, d1 = v1 - mu;
    float vs = d0 * d0 + d1 * d1;
    #pragma unroll
    for (int o = 16; o > 0; o >>= 1) vs += __shfl_xor_sync(0xffffffffu, vs, o);
    float inv = rsqrtf(vs * (1.f / 64.f) + 1e-5f);
    row[lane]      = d0 * inv * w[lane]      + b[lane];
    row[lane + 32] = d1 * inv * w[lane + 32] + b[lane + 32];
}

// ---------------------------------------------------------------------------
// Causal flash attention (fp32). Q tile = 64 rows, KV tile = 32 rows.
// ---------------------------------------------------------------------------
__global__ __launch_bounds__(256)
void flash_attn(const float* __restrict__ Q, const float* __restrict__ Kp,
                const float* __restrict__ V, float* __restrict__ O)
{
    const int TQ = 64, TK = 32;
    __shared__ float Qs[TQ][HDIM + 1];
    __shared__ float Ks[TK][HDIM + 1];
    __shared__ float Vs[TK][HDIM];
    __shared__ float Ps[TQ][TK + 1];

    int qt = blockIdx.x;
    int h  = blockIdx.y;
    int bb = blockIdx.z;
    int tid = threadIdx.x;
    int c4  = tid & 3;
    int r   = tid >> 2;

    int q0 = qt * TQ;
    int qg = q0 + r;

    for (int i = tid; i < TQ * HDIM; i += 256) {
        int rr = i >> 6, d = i & 63;
        Qs[rr][d] = Q[(size_t)(bb * TLEN + q0 + rr) * EDIM + h * HDIM + d];
    }

    float acc[16];
    #pragma unroll
    for (int j = 0; j < 16; j++) acc[j] = 0.f;
    float m = -INFINITY, l = 0.f;

    int nkt = 2 * qt + 2;
    for (int kt = 0; kt < nkt; kt++) {
        __syncthreads();
        int k0 = kt * TK;
        for (int i = tid; i < TK * HDIM; i += 256) {
            int rr = i >> 6, d = i & 63;
            size_t gi = (size_t)(bb * TLEN + k0 + rr) * EDIM + h * HDIM + d;
            Ks[rr][d] = Kp[gi];
            Vs[rr][d] = V[gi];
        }
        __syncthreads();

        float s[8];
        #pragma unroll
        for (int j = 0; j < 8; j++) s[j] = 0.f;
        int kc0 = c4 * 8;
        #pragma unroll 8
        for (int d = 0; d < HDIM; d++) {
            float qv = Qs[r][d];
            #pragma unroll
            for (int j = 0; j < 8; j++) s[j] += qv * Ks[kc0 + j][d];
        }

        float mloc = -INFINITY;
        #pragma unroll
        for (int j = 0; j < 8; j++) {
            s[j] *= 0.125f;
            if (k0 + kc0 + j > qg) s[j] = -INFINITY;
            mloc = fmaxf(mloc, s[j]);
        }
        mloc = fmaxf(mloc, __shfl_xor_sync(0xffffffffu, mloc, 1));
        mloc = fmaxf(mloc, __shfl_xor_sync(0xffffffffu, mloc, 2));
        float mnew = fmaxf(m, mloc);

        float lloc = 0.f;
        #pragma unroll
        for (int j = 0; j < 8; j++) {
            float p = __expf(s[j] - mnew);
            Ps[r][kc0 + j] = p;
            lloc += p;
        }
        lloc += __shfl_xor_sync(0xffffffffu, lloc, 1);
        lloc += __shfl_xor_sync(0xffffffffu, lloc, 2);

        float corr = __expf(m - mnew);
        l = l * corr + lloc;
        m = mnew;
        #pragma unroll
        for (int j = 0; j < 16; j++) acc[j] *= corr;
        __syncthreads();

        #pragma unroll 4
        for (int k = 0; k < TK; k++) {
            float p = Ps[r][k];
            #pragma unroll
            for (int j = 0; j < 16; j++) acc[j] += p * Vs[k][c4 + 4 * j];
        }
    }

    float inv = 1.f / l;
    size_t ob = (size_t)(bb * TLEN + q0 + r) * EDIM + h * HDIM;
    #pragma unroll
    for (int j = 0; j < 16; j++)
        O[ob + c4 + 4 * j] = acc[j] * inv;
}

// ---------------------------------------------------------------------------
// Launch
// ---------------------------------------------------------------------------
extern "C" void kernel_launch(void* const* d_in, const int* in_sizes, int n_in,
                              void* d_out, int out_size)
{
    const float* x     = (const float*)d_in[0];
    const float* Wk    = (const float*)d_in[1];
    const float* Wq    = (const float*)d_in[2];
    const float* Wv    = (const float*)d_in[3];
    const float* Wo    = (const float*)d_in[4];
    const float* bo    = (const float*)d_in[5];
    const float* kln_w = (const float*)d_in[6];
    const float* kln_b = (const float*)d_in[7];
    const float* qln_w = (const float*)d_in[8];
    const float* qln_b = (const float*)d_in[9];
    float* out = (float*)d_out;

    float *q, *k, *v, *att;
    cudaGetSymbolAddress((void**)&q,   g_q);
    cudaGetSymbolAddress((void**)&k,   g_k);
    cudaGetSymbolAddress((void**)&v,   g_v);
    cudaGetSymbolAddress((void**)&att, g_att);

    static int smem_set = 0;
    if (!smem_set) {
        cudaFuncSetAttribute(gemm_tf32,
                             cudaFuncAttributeMaxDynamicSharedMemorySize,
                             GEMM_SMEM);
        smem_set = 1;
    }

    dim3 gemmGrid(EDIM / 128, MROWS / 128);   // (8, 32)
    gemm_tf32<<<gemmGrid, 256, GEMM_SMEM>>>(x, Wq, nullptr, q, MROWS, EDIM, EDIM);
    gemm_tf32<<<gemmGrid, 256, GEMM_SMEM>>>(x, Wk, nullptr, k, MROWS, EDIM, EDIM);
    gemm_tf32<<<gemmGrid, 256, GEMM_SMEM>>>(x, Wv, nullptr, v, MROWS, EDIM, EDIM);

    int nrows = MROWS * HEADS;                // 65536 rows of 64
    int lnBlocks = nrows * 32 / 256;          // 8192
    head_layernorm<<<lnBlocks, 256>>>(q, qln_w, qln_b, nrows);
    head_layernorm<<<lnBlocks, 256>>>(k, kln_w, kln_b, nrows);

    dim3 attGrid(TLEN / 64, HEADS, BATCH);    // (32, 16, 2)
    flash_attn<<<attGrid, 256>>>(q, k, v, att);

    gemm_tf32<<<gemmGrid, 256, GEMM_SMEM>>>(att, Wo, bo, out, MROWS, EDIM, EDIM);
}

// round 3
// speedup vs baseline: 1.3125x; 1.3125x over previous
#include <cuda_runtime.h>
#include <cuda_bf16.h>
#include <math.h>
#include <stdint.h>

#define HEADS 16
#define HDIM  64
#define BATCH 2
#define TLEN  2048
#define EDIM  1024
#define MROWS (BATCH*TLEN)   // 4096

// Scratch (allocation-free rule: __device__ globals)
__device__ float g_q[MROWS*EDIM];
__device__ float g_k[MROWS*EDIM];
__device__ float g_v[MROWS*EDIM];
__device__ float g_att[MROWS*EDIM];

// ---------------------------------------------------------------------------
// bf16 helpers
// ---------------------------------------------------------------------------
__device__ __forceinline__ void bsplit(float v, __nv_bfloat16& h, __nv_bfloat16& l) {
    h = __float2bfloat16_rn(v);
    l = __float2bfloat16_rn(v - __bfloat162float(h));
}
__device__ __forceinline__ unsigned pk(__nv_bfloat16 a, __nv_bfloat16 b) {
    __nv_bfloat162 t; t.x = a; t.y = b;           // a = low half (k even)
    return *reinterpret_cast<unsigned*>(&t);
}
__device__ __forceinline__ void mma16(float* c, const unsigned* a, const unsigned* b) {
    asm volatile(
        "mma.sync.aligned.m16n8k16.row.col.f32.bf16.bf16.f32 "
        "{%0,%1,%2,%3}, {%4,%5,%6,%7}, {%8,%9}, {%0,%1,%2,%3};\n"
        : "+f"(c[0]), "+f"(c[1]), "+f"(c[2]), "+f"(c[3])
        : "r"(a[0]), "r"(a[1]), "r"(a[2]), "r"(a[3]), "r"(b[0]), "r"(b[1]));
}

// ---------------------------------------------------------------------------
// bf16x3 tensor-core GEMM: C[M,N] = A[M,K] @ B[K,N] (+ bias)
// BM=BN=128, BK=16, 256 threads (8 warps, 2x4 of 64x32 warp tiles).
// smem: packed k-pair u32, layout [kpair][row], stride 136 (conflict-free:
// bank = (8*kpair + row) mod 32 is a lane permutation for the frag pattern).
// ---------------------------------------------------------------------------
#define SSTR 136
#define KP   8      // k-pairs per 16-K chunk

__global__ __launch_bounds__(256, 1)
void gemm_bf16x3(const float* __restrict__ A, const float* __restrict__ B,
                 const float* __restrict__ bias, float* __restrict__ C,
                 int M, int N, int K)
{
    __shared__ uint32_t SA[2][2][KP * SSTR];   // [stage][hi/lo]
    __shared__ uint32_t SB[2][2][KP * SSTR];

    const int tid  = threadIdx.x;
    const int lane = tid & 31;
    const int w    = tid >> 5;
    const int warpM = (w >> 2) * 64;
    const int warpN = (w & 3) * 32;
    const int gid  = lane >> 2;    // 0..7
    const int tg   = lane & 3;     // 0..3

    const int brow = blockIdx.y * 128;
    const int bcol = blockIdx.x * 128;

    // gmem load mapping
    const int am  = tid >> 1;          // A row in tile 0..127
    const int akp = (tid & 1) * 4;     // A k-pair base: 0 or 4
    const int bkp = tid >> 5;          // B k-pair 0..7
    const int bn  = (tid & 31) * 4;    // B col 0..124

    const float* Ag = A + (size_t)(brow + am) * K + akp * 2;
    const float* Bg = B + (size_t)(bkp * 2) * N + (bcol + bn);

    float4 ra0, ra1, rb0, rb1;
    ra0 = *(const float4*)(Ag);
    ra1 = *(const float4*)(Ag + 4);
    rb0 = *(const float4*)(Bg);
    rb1 = *(const float4*)(Bg + N);

    float acc[4][4][4];
    #pragma unroll
    for (int mt = 0; mt < 4; mt++)
        #pragma unroll
        for (int nt = 0; nt < 4; nt++)
            #pragma unroll
            for (int i = 0; i < 4; i++) acc[mt][nt][i] = 0.f;

    // ---- store stage s from prefetch regs ----
    auto store_stage = [&](int s) {
        float va[8] = {ra0.x, ra0.y, ra0.z, ra0.w, ra1.x, ra1.y, ra1.z, ra1.w};
        #pragma unroll
        for (int p = 0; p < 4; p++) {
            __nv_bfloat16 h0, l0, h1, l1;
            bsplit(va[2*p],   h0, l0);
            bsplit(va[2*p+1], h1, l1);
            SA[s][0][(akp + p) * SSTR + am] = pk(h0, h1);
            SA[s][1][(akp + p) * SSTR + am] = pk(l0, l1);
        }
        float e0[4] = {rb0.x, rb0.y, rb0.z, rb0.w};
        float e1[4] = {rb1.x, rb1.y, rb1.z, rb1.w};
        uint32_t bh[4], bl[4];
        #pragma unroll
        for (int j = 0; j < 4; j++) {
            __nv_bfloat16 h0, l0, h1, l1;
            bsplit(e0[j], h0, l0);
            bsplit(e1[j], h1, l1);
            bh[j] = pk(h0, h1);
            bl[j] = pk(l0, l1);
        }
        *(uint4*)&SB[s][0][bkp * SSTR + bn] = make_uint4(bh[0], bh[1], bh[2], bh[3]);
        *(uint4*)&SB[s][1][bkp * SSTR + bn] = make_uint4(bl[0], bl[1], bl[2], bl[3]);
    };

    store_stage(0);
    __syncthreads();

    const int NKI = K / 16;
    for (int t = 0; t < NKI; t++) {
        int buf = t & 1;
        if (t + 1 < NKI) {
            const float* Ag2 = Ag + (t + 1) * 16;
            ra0 = *(const float4*)(Ag2);
            ra1 = *(const float4*)(Ag2 + 4);
            const float* Bg2 = Bg + (size_t)(t + 1) * 16 * N;
            rb0 = *(const float4*)(Bg2);
            rb1 = *(const float4*)(Bg2 + N);
        }

        // fragments
        unsigned ah[4][4], al[4][4], bh2[4][2], bl2[4][2];
        #pragma unroll
        for (int mt = 0; mt < 4; mt++) {
            int r = warpM + mt * 16 + gid;
            ah[mt][0] = SA[buf][0][tg * SSTR + r];
            ah[mt][1] = SA[buf][0][tg * SSTR + r + 8];
            ah[mt][2] = SA[buf][0][(tg + 4) * SSTR + r];
            ah[mt][3] = SA[buf][0][(tg + 4) * SSTR + r + 8];
            al[mt][0] = SA[buf][1][tg * SSTR + r];
            al[mt][1] = SA[buf][1][tg * SSTR + r + 8];
            al[mt][2] = SA[buf][1][(tg + 4) * SSTR + r];
            al[mt][3] = SA[buf][1][(tg + 4) * SSTR + r + 8];
        }
        #pragma unroll
        for (int nt = 0; nt < 4; nt++) {
            int n = warpN + nt * 8 + gid;
            bh2[nt][0] = SB[buf][0][tg * SSTR + n];
            bh2[nt][1] = SB[buf][0][(tg + 4) * SSTR + n];
            bl2[nt][0] = SB[buf][1][tg * SSTR + n];
            bl2[nt][1] = SB[buf][1][(tg + 4) * SSTR + n];
        }
        #pragma unroll
        for (int mt = 0; mt < 4; mt++)
            #pragma unroll
            for (int nt = 0; nt < 4; nt++) {
                mma16(acc[mt][nt], ah[mt], bl2[nt]);
                mma16(acc[mt][nt], al[mt], bh2[nt]);
                mma16(acc[mt][nt], ah[mt], bh2[nt]);
            }

        if (t + 1 < NKI) {
            store_stage(buf ^ 1);
            __syncthreads();
        }
    }

    // epilogue
    #pragma unroll
    for (int mt = 0; mt < 4; mt++) {
        int r0 = brow + warpM + mt * 16 + gid;
        #pragma unroll
        for (int nt = 0; nt < 4; nt++) {
            int c0 = bcol + warpN + nt * 8 + tg * 2;
            float bx = 0.f, by = 0.f;
            if (bias) { bx = bias[c0]; by = bias[c0 + 1]; }
            float2 o0 = make_float2(acc[mt][nt][0] + bx, acc[mt][nt][1] + by);
            float2 o1 = make_float2(acc[mt][nt][2] + bx, acc[mt][nt][3] + by);
            *(float2*)(&C[(size_t)r0 * N + c0])       = o0;
            *(float2*)(&C[(size_t)(r0 + 8) * N + c0]) = o1;
        }
    }
}

// ---------------------------------------------------------------------------
// Per-head LayerNorm over head dim (64), q and k in one launch (grid.y).
// ---------------------------------------------------------------------------
__global__ __launch_bounds__(256)
void head_layernorm2(float* __restrict__ q, float* __restrict__ k,
                     const float* __restrict__ qw, const float* __restrict__ qb,
                     const float* __restrict__ kw, const float* __restrict__ kb,
                     int nrows)
{
    float* x       = blockIdx.y ? k  : q;
    const float* w = blockIdx.y ? kw : qw;
    const float* b = blockIdx.y ? kb : qb;

    int warp = (blockIdx.x * blockDim.x + threadIdx.x) >> 5;
    int lane = threadIdx.x & 31;
    if (warp >= nrows) return;
    float* row = x + (size_t)warp * HDIM;
    float v0 = row[lane];
    float v1 = row[lane + 32];
    float s = v0 + v1;
    #pragma unroll
    for (int o = 16; o > 0; o >>= 1) s += __shfl_xor_sync(0xffffffffu, s, o);
    float mu = s * (1.f / 64.f);
    float d0 = v0 - mu, d1 = v1 - mu;
    float vs = d0 * d0 + d1 * d1;
    #pragma unroll
    for (int o = 16; o > 0; o >>= 1) vs += __shfl_xor_sync(0xffffffffu, vs, o);
    float inv = rsqrtf(vs * (1.f / 64.f) + 1e-5f);
    row[lane]      = d0 * inv * w[lane]      + b[lane];
    row[lane + 32] = d1 * inv * w[lane + 32] + b[lane + 32];
}

// ---------------------------------------------------------------------------
// Causal flash attention (fp32). Q tile = 64 rows, KV tile = 32 rows.
// ---------------------------------------------------------------------------
__global__ __launch_bounds__(256)
void flash_attn(const float* __restrict__ Q, const float* __restrict__ Kp,
                const float* __restrict__ V, float* __restrict__ O)
{
    const int TQ = 64, TK = 32;
    __shared__ float Qs[TQ][HDIM + 1];
    __shared__ float Ks[TK][HDIM + 1];
    __shared__ float Vs[TK][HDIM];
    __shared__ float Ps[TQ][TK + 1];

    int qt = blockIdx.x;
    int h  = blockIdx.y;
    int bb = blockIdx.z;
    int tid = threadIdx.x;
    int c4  = tid & 3;
    int r   = tid >> 2;

    int q0 = qt * TQ;
    int qg = q0 + r;

    for (int i = tid; i < TQ * HDIM; i += 256) {
        int rr = i >> 6, d = i & 63;
        Qs[rr][d] = Q[(size_t)(bb * TLEN + q0 + rr) * EDIM + h * HDIM + d];
    }

    float acc[16];
    #pragma unroll
    for (int j = 0; j < 16; j++) acc[j] = 0.f;
    float m = -INFINITY, l = 0.f;

    int nkt = 2 * qt + 2;
    for (int kt = 0; kt < nkt; kt++) {
        __syncthreads();
        int k0 = kt * TK;
        for (int i = tid; i < TK * HDIM; i += 256) {
            int rr = i >> 6, d = i & 63;
            size_t gi = (size_t)(bb * TLEN + k0 + rr) * EDIM + h * HDIM + d;
            Ks[rr][d] = Kp[gi];
            Vs[rr][d] = V[gi];
        }
        __syncthreads();

        float s[8];
        #pragma unroll
        for (int j = 0; j < 8; j++) s[j] = 0.f;
        int kc0 = c4 * 8;
        #pragma unroll 8
        for (int d = 0; d < HDIM; d++) {
            float qv = Qs[r][d];
            #pragma unroll
            for (int j = 0; j < 8; j++) s[j] += qv * Ks[kc0 + j][d];
        }

        float mloc = -INFINITY;
        #pragma unroll
        for (int j = 0; j < 8; j++) {
            s[j] *= 0.125f;
            if (k0 + kc0 + j > qg) s[j] = -INFINITY;
            mloc = fmaxf(mloc, s[j]);
        }
        mloc = fmaxf(mloc, __shfl_xor_sync(0xffffffffu, mloc, 1));
        mloc = fmaxf(mloc, __shfl_xor_sync(0xffffffffu, mloc, 2));
        float mnew = fmaxf(m, mloc);

        float lloc = 0.f;
        #pragma unroll
        for (int j = 0; j < 8; j++) {
            float p = __expf(s[j] - mnew);
            Ps[r][kc0 + j] = p;
            lloc += p;
        }
        lloc += __shfl_xor_sync(0xffffffffu, lloc, 1);
        lloc += __shfl_xor_sync(0xffffffffu, lloc, 2);

        float corr = __expf(m - mnew);
        l = l * corr + lloc;
        m = mnew;
        #pragma unroll
        for (int j = 0; j < 16; j++) acc[j] *= corr;
        __syncthreads();

        #pragma unroll 4
        for (int k = 0; k < TK; k++) {
            float p = Ps[r][k];
            #pragma unroll
            for (int j = 0; j < 16; j++) acc[j] += p * Vs[k][c4 + 4 * j];
        }
    }

    float inv = 1.f / l;
    size_t ob = (size_t)(bb * TLEN + q0 + r) * EDIM + h * HDIM;
    #pragma unroll
    for (int j = 0; j < 16; j++)
        O[ob + c4 + 4 * j] = acc[j] * inv;
}

// ---------------------------------------------------------------------------
// Launch
// ---------------------------------------------------------------------------
extern "C" void kernel_launch(void* const* d_in, const int* in_sizes, int n_in,
                              void* d_out, int out_size)
{
    const float* x     = (const float*)d_in[0];
    const float* Wk    = (const float*)d_in[1];
    const float* Wq    = (const float*)d_in[2];
    const float* Wv    = (const float*)d_in[3];
    const float* Wo    = (const float*)d_in[4];
    const float* bo    = (const float*)d_in[5];
    const float* kln_w = (const float*)d_in[6];
    const float* kln_b = (const float*)d_in[7];
    const float* qln_w = (const float*)d_in[8];
    const float* qln_b = (const float*)d_in[9];
    float* out = (float*)d_out;

    float *q, *k, *v, *att;
    cudaGetSymbolAddress((void**)&q,   g_q);
    cudaGetSymbolAddress((void**)&k,   g_k);
    cudaGetSymbolAddress((void**)&v,   g_v);
    cudaGetSymbolAddress((void**)&att, g_att);

    dim3 gemmGrid(EDIM / 128, MROWS / 128);   // (8, 32)
    gemm_bf16x3<<<gemmGrid, 256>>>(x, Wq, nullptr, q, MROWS, EDIM, EDIM);
    gemm_bf16x3<<<gemmGrid, 256>>>(x, Wk, nullptr, k, MROWS, EDIM, EDIM);
    gemm_bf16x3<<<gemmGrid, 256>>>(x, Wv, nullptr, v, MROWS, EDIM, EDIM);

    int nrows = MROWS * HEADS;                // 65536 rows of 64
    dim3 lnGrid(nrows * 32 / 256, 2);         // (8192, 2)
    head_layernorm2<<<lnGrid, 256>>>(q, k, qln_w, qln_b, kln_w, kln_b, nrows);

    dim3 attGrid(TLEN / 64, HEADS, BATCH);    // (32, 16, 2)
    flash_attn<<<attGrid, 256>>>(q, k, v, att);

    gemm_bf16x3<<<gemmGrid, 256>>>(att, Wo, bo, out, MROWS, EDIM, EDIM);
}

// round 5
// speedup vs baseline: 1.4211x; 1.0827x over previous
#include <cuda_runtime.h>
#include <cuda_bf16.h>
#include <math.h>
#include <stdint.h>

#define HEADS 16
#define HDIM  64
#define BATCH 2
#define TLEN  2048
#define EDIM  1024
#define MROWS (BATCH*TLEN)   // 4096

// ---------------------------------------------------------------------------
// Scratch (allocation-free rule: __device__ globals)
// ---------------------------------------------------------------------------
__device__ float g_q[MROWS*EDIM];
__device__ float g_k[MROWS*EDIM];
__device__ float g_v[MROWS*EDIM];
__device__ float g_att[MROWS*EDIM];
__device__ __align__(16) __nv_bfloat16 g_xh[MROWS*EDIM], g_xl[MROWS*EDIM];
__device__ __align__(16) __nv_bfloat16 g_ah[MROWS*EDIM], g_al[MROWS*EDIM];
__device__ __align__(16) __nv_bfloat16 g_wh[4*EDIM*EDIM], g_wl[4*EDIM*EDIM];

// ---------------------------------------------------------------------------
// helpers
// ---------------------------------------------------------------------------
__device__ __forceinline__ uint32_t smem_to_u32(const void* p) {
    uint32_t a;
    asm("{ .reg .u64 t; cvta.to.shared.u64 t, %1; cvt.u32.u64 %0, t; }"
        : "=r"(a) : "l"(p));
    return a;
}
__device__ __forceinline__ void cp16(uint32_t smem, const void* g) {
    asm volatile("cp.async.cg.shared.global [%0], [%1], 16;\n"
                 :: "r"(smem), "l"(g));
}
#define CP_COMMIT() asm volatile("cp.async.commit_group;\n" ::: "memory")
#define CP_WAIT(N)  asm volatile("cp.async.wait_group %0;\n" :: "n"(N) : "memory")

__device__ __forceinline__ void bsplit(float v, __nv_bfloat16& h, __nv_bfloat16& l) {
    h = __float2bfloat16_rn(v);
    l = __float2bfloat16_rn(v - __bfloat162float(h));
}
__device__ __forceinline__ unsigned pk2(__nv_bfloat16 a, __nv_bfloat16 b) {
    __nv_bfloat162 t; t.x = a; t.y = b;
    return *reinterpret_cast<unsigned*>(&t);
}
__device__ __forceinline__ void mma16(float* c, const unsigned* a, const unsigned* b) {
    asm volatile(
        "mma.sync.aligned.m16n8k16.row.col.f32.bf16.bf16.f32 "
        "{%0,%1,%2,%3}, {%4,%5,%6,%7}, {%8,%9}, {%0,%1,%2,%3};\n"
        : "+f"(c[0]), "+f"(c[1]), "+f"(c[2]), "+f"(c[3])
        : "r"(a[0]), "r"(a[1]), "r"(a[2]), "r"(a[3]), "r"(b[0]), "r"(b[1]));
}

// ---------------------------------------------------------------------------
// fp32 -> bf16 hi/lo split (elementwise, float4 vectorized)
// ---------------------------------------------------------------------------
__global__ __launch_bounds__(256)
void conv_split(const float4* __restrict__ in, uint2* __restrict__ oh,
                uint2* __restrict__ ol, int n4)
{
    int i = blockIdx.x * blockDim.x + threadIdx.x;
    if (i >= n4) return;
    float4 v = in[i];
    __nv_bfloat16 h0, l0, h1, l1, h2, l2, h3, l3;
    bsplit(v.x, h0, l0); bsplit(v.y, h1, l1);
    bsplit(v.z, h2, l2); bsplit(v.w, h3, l3);
    oh[i] = make_uint2(pk2(h0, h1), pk2(h2, h3));
    ol[i] = make_uint2(pk2(l0, l1), pk2(l2, l3));
}

// ---------------------------------------------------------------------------
// Weight transpose + bf16 hi/lo split: Wt[n][k] = W[k][n], 4 weights (grid.z)
// ---------------------------------------------------------------------------
__global__ __launch_bounds__(256)
void wtrans(const float* __restrict__ W0, const float* __restrict__ W1,
            const float* __restrict__ W2, const float* __restrict__ W3,
            __nv_bfloat16* __restrict__ oh, __nv_bfloat16* __restrict__ ol)
{
    __shared__ float tile[32][33];
    int wsel = blockIdx.z;
    const float* W = wsel == 0 ? W0 : wsel == 1 ? W1 : wsel == 2 ? W2 : W3;
    size_t obase = (size_t)wsel * EDIM * EDIM;
    int n0 = blockIdx.x * 32, k0 = blockIdx.y * 32;
    int tx = threadIdx.x & 31, ty = threadIdx.x >> 5;   // (32 x 8)
    #pragma unroll
    for (int j = 0; j < 4; j++)
        tile[ty + j * 8][tx] = W[(size_t)(k0 + ty + j * 8) * EDIM + n0 + tx];
    __syncthreads();
    #pragma unroll
    for (int j = 0; j < 4; j++) {
        float v = tile[tx][ty + j * 8];
        __nv_bfloat16 h, l;
        bsplit(v, h, l);
        size_t o = obase + (size_t)(n0 + ty + j * 8) * EDIM + k0 + tx;
        oh[o] = h; ol[o] = l;
    }
}

// ---------------------------------------------------------------------------
// bf16x3 GEMM (legacy mma, cp.async): C[M,1024] = A @ Wt^T (+ bias)
// Block 256x128, BK=32, 8 warps x (64x64). A=[m][k] hi/lo, B=Wt[n][k] hi/lo.
// smem rows RS=80 B (64 data + 16 pad): fragment LDS bank = 20*gid+tg mod 32
// is a full 32-lane permutation -> conflict-free. 2-stage cp.async pipeline.
// ---------------------------------------------------------------------------
#define RS      80
#define OFF_AL  (256*RS)             // 20480
#define OFF_BH  (2*256*RS)           // 40960
#define OFF_BL  (2*256*RS+128*RS)    // 51200
#define STAGE_B (2*256*RS+2*128*RS)  // 61440
#define GEMM_SMEM (2*STAGE_B)        // 122880
#define NKC     (EDIM/32)            // 32 chunks

__global__ __launch_bounds__(256, 1)
void gemm_bf(const __nv_bfloat16* __restrict__ Ah, const __nv_bfloat16* __restrict__ Al,
             const __nv_bfloat16* __restrict__ Bh, const __nv_bfloat16* __restrict__ Bl,
             const float* __restrict__ bias, float* __restrict__ C)
{
    extern __shared__ char sm[];
    const uint32_t smu = smem_to_u32(sm);

    const int tid  = threadIdx.x;
    const int lane = tid & 31;
    const int w    = tid >> 5;
    const int gid  = lane >> 2;        // 0..7
    const int tg   = lane & 3;         // 0..3
    const int warpM = (w & 3) * 64;
    const int warpN = (w >> 2) * 64;

    const int brow = blockIdx.y * 256;
    const int bcol = blockIdx.x * 128;

    const int lr = tid >> 2;           // 0..63
    const int lc = tid & 3;            // 0..3 (16B col)

    // ---- async load of one stage ----
    auto load_stage = [&](int s, int chunk) {
        uint32_t sb = smu + s * STAGE_B;
        int kel = chunk * 32 + lc * 8;
        #pragma unroll
        for (int i = 0; i < 4; i++) {
            int row = lr + 64 * i;
            size_t gi = (size_t)(brow + row) * EDIM + kel;
            uint32_t so = (uint32_t)(row * RS + lc * 16);
            cp16(sb + so,          Ah + gi);
            cp16(sb + OFF_AL + so, Al + gi);
        }
        #pragma unroll
        for (int i = 0; i < 2; i++) {
            int row = lr + 64 * i;
            size_t gi = (size_t)(bcol + row) * EDIM + kel;
            uint32_t so = (uint32_t)(row * RS + lc * 16);
            cp16(sb + OFF_BH + so, Bh + gi);
            cp16(sb + OFF_BL + so, Bl + gi);
        }
        CP_COMMIT();
    };

    float acc[4][8][4];
    #pragma unroll
    for (int mt = 0; mt < 4; mt++)
        #pragma unroll
        for (int nt = 0; nt < 8; nt++)
            #pragma unroll
            for (int i = 0; i < 4; i++) acc[mt][nt][i] = 0.f;

    load_stage(0, 0);

    for (int c = 0; c < NKC; c++) {
        int s = c & 1;
        if (c + 1 < NKC) {
            load_stage(s ^ 1, c + 1);
            CP_WAIT(1);
        } else {
            CP_WAIT(0);
        }
        __syncthreads();

        const char* base = sm + s * STAGE_B;
        #pragma unroll
        for (int ks = 0; ks < 2; ks++) {
            int koff = ks * 32 + tg * 4;
            unsigned bh[8][2], bl[8][2];
            #pragma unroll
            for (int nt = 0; nt < 8; nt++) {
                int n = warpN + nt * 8 + gid;
                const char* ph = base + OFF_BH + n * RS + koff;
                const char* pl = base + OFF_BL + n * RS + koff;
                bh[nt][0] = *(const uint32_t*)(ph);
                bh[nt][1] = *(const uint32_t*)(ph + 16);
                bl[nt][0] = *(const uint32_t*)(pl);
                bl[nt][1] = *(const uint32_t*)(pl + 16);
            }
            #pragma unroll
            for (int mt = 0; mt < 4; mt++) {
                int r = warpM + mt * 16 + gid;
                const char* pa = base + r * RS + koff;
                const char* pb = base + OFF_AL + r * RS + koff;
                unsigned ah[4], al[4];
                ah[0] = *(const uint32_t*)(pa);
                ah[1] = *(const uint32_t*)(pa + 8 * RS);
                ah[2] = *(const uint32_t*)(pa + 16);
                ah[3] = *(const uint32_t*)(pa + 8 * RS + 16);
                al[0] = *(const uint32_t*)(pb);
                al[1] = *(const uint32_t*)(pb + 8 * RS);
                al[2] = *(const uint32_t*)(pb + 16);
                al[3] = *(const uint32_t*)(pb + 8 * RS + 16);
                #pragma unroll
                for (int nt = 0; nt < 8; nt++) {
                    mma16(acc[mt][nt], ah, bl[nt]);
                    mma16(acc[mt][nt], al, bh[nt]);
                    mma16(acc[mt][nt], ah, bh[nt]);
                }
            }
        }
        __syncthreads();
    }

    // epilogue
    #pragma unroll
    for (int mt = 0; mt < 4; mt++) {
        int r0 = brow + warpM + mt * 16 + gid;
        #pragma unroll
        for (int nt = 0; nt < 8; nt++) {
            int c0 = bcol + warpN + nt * 8 + tg * 2;
            float bx = 0.f, by = 0.f;
            if (bias) { bx = bias[c0]; by = bias[c0 + 1]; }
            *(float2*)(&C[(size_t)r0 * EDIM + c0]) =
                make_float2(acc[mt][nt][0] + bx, acc[mt][nt][1] + by);
            *(float2*)(&C[(size_t)(r0 + 8) * EDIM + c0]) =
                make_float2(acc[mt][nt][2] + bx, acc[mt][nt][3] + by);
        }
    }
}

// ---------------------------------------------------------------------------
// Per-head LayerNorm over head dim (64), q and k in one launch (grid.y).
// ---------------------------------------------------------------------------
__global__ __launch_bounds__(256)
void head_layernorm2(float* __restrict__ q, float* __restrict__ k,
                     const float* __restrict__ qw, const float* __restrict__ qb,
                     const float* __restrict__ kw, const float* __restrict__ kb,
                     int nrows)
{
    float* x       = blockIdx.y ? k  : q;
    const float* w = blockIdx.y ? kw : qw;
    const float* b = blockIdx.y ? kb : qb;

    int warp = (blockIdx.x * blockDim.x + threadIdx.x) >> 5;
    int lane = threadIdx.x & 31;
    if (warp >= nrows) return;
    float* row = x + (size_t)warp * HDIM;
    float v0 = row[lane];
    float v1 = row[lane + 32];
    float s = v0 + v1;
    #pragma unroll
    for (int o = 16; o > 0; o >>= 1) s += __shfl_xor_sync(0xffffffffu, s, o);
    float mu = s * (1.f / 64.f);
    float d0 = v0 - mu, d1 = v1 - mu;
    float vs = d0 * d0 + d1 * d1;
    #pragma unroll
    for (int o = 16; o > 0; o >>= 1) vs += __shfl_xor_sync(0xffffffffu, vs, o);
    float inv = rsqrtf(vs * (1.f / 64.f) + 1e-5f);
    row[lane]      = d0 * inv * w[lane]      + b[lane];
    row[lane + 32] = d1 * inv * w[lane + 32] + b[lane + 32];
}

// ---------------------------------------------------------------------------
// Causal flash attention (fp32). Q tile = 64 rows, KV tile = 32 rows.
// ---------------------------------------------------------------------------
__global__ __launch_bounds__(256)
void flash_attn(const float* __restrict__ Q, const float* __restrict__ Kp,
                const float* __restrict__ V, float* __restrict__ O)
{
    const int TQ = 64, TK = 32;
    __shared__ float Qs[TQ][HDIM + 1];
    __shared__ float Ks[TK][HDIM + 1];
    __shared__ float Vs[TK][HDIM];
    __shared__ float Ps[TQ][TK + 1];

    int qt = blockIdx.x;
    int h  = blockIdx.y;
    int bb = blockIdx.z;
    int tid = threadIdx.x;
    int c4  = tid & 3;
    int r   = tid >> 2;

    int q0 = qt * TQ;
    int qg = q0 + r;

    for (int i = tid; i < TQ * HDIM; i += 256) {
        int rr = i >> 6, d = i & 63;
        Qs[rr][d] = Q[(size_t)(bb * TLEN + q0 + rr) * EDIM + h * HDIM + d];
    }

    float acc[16];
    #pragma unroll
    for (int j = 0; j < 16; j++) acc[j] = 0.f;
    float m = -INFINITY, l = 0.f;

    int nkt = 2 * qt + 2;
    for (int kt = 0; kt < nkt; kt++) {
        __syncthreads();
        int k0 = kt * TK;
        for (int i = tid; i < TK * HDIM; i += 256) {
            int rr = i >> 6, d = i & 63;
            size_t gi = (size_t)(bb * TLEN + k0 + rr) * EDIM + h * HDIM + d;
            Ks[rr][d] = Kp[gi];
            Vs[rr][d] = V[gi];
        }
        __syncthreads();

        float s[8];
        #pragma unroll
        for (int j = 0; j < 8; j++) s[j] = 0.f;
        int kc0 = c4 * 8;
        #pragma unroll 8
        for (int d = 0; d < HDIM; d++) {
            float qv = Qs[r][d];
            #pragma unroll
            for (int j = 0; j < 8; j++) s[j] += qv * Ks[kc0 + j][d];
        }

        float mloc = -INFINITY;
        #pragma unroll
        for (int j = 0; j < 8; j++) {
            s[j] *= 0.125f;
            if (k0 + kc0 + j > qg) s[j] = -INFINITY;
            mloc = fmaxf(mloc, s[j]);
        }
        mloc = fmaxf(mloc, __shfl_xor_sync(0xffffffffu, mloc, 1));
        mloc = fmaxf(mloc, __shfl_xor_sync(0xffffffffu, mloc, 2));
        float mnew = fmaxf(m, mloc);

        float lloc = 0.f;
        #pragma unroll
        for (int j = 0; j < 8; j++) {
            float p = __expf(s[j] - mnew);
            Ps[r][kc0 + j] = p;
            lloc += p;
        }
        lloc += __shfl_xor_sync(0xffffffffu, lloc, 1);
        lloc += __shfl_xor_sync(0xffffffffu, lloc, 2);

        float corr = __expf(m - mnew);
        l = l * corr + lloc;
        m = mnew;
        #pragma unroll
        for (int j = 0; j < 16; j++) acc[j] *= corr;
        __syncthreads();

        #pragma unroll 4
        for (int k = 0; k < TK; k++) {
            float p = Ps[r][k];
            #pragma unroll
            for (int j = 0; j < 16; j++) acc[j] += p * Vs[k][c4 + 4 * j];
        }
    }

    float inv = 1.f / l;
    size_t ob = (size_t)(bb * TLEN + q0 + r) * EDIM + h * HDIM;
    #pragma unroll
    for (int j = 0; j < 16; j++)
        O[ob + c4 + 4 * j] = acc[j] * inv;
}

// ---------------------------------------------------------------------------
// Launch
// ---------------------------------------------------------------------------
extern "C" void kernel_launch(void* const* d_in, const int* in_sizes, int n_in,
                              void* d_out, int out_size)
{
    const float* x     = (const float*)d_in[0];
    const float* Wk    = (const float*)d_in[1];
    const float* Wq    = (const float*)d_in[2];
    const float* Wv    = (const float*)d_in[3];
    const float* Wo    = (const float*)d_in[4];
    const float* bo    = (const float*)d_in[5];
    const float* kln_w = (const float*)d_in[6];
    const float* kln_b = (const float*)d_in[7];
    const float* qln_w = (const float*)d_in[8];
    const float* qln_b = (const float*)d_in[9];
    float* out = (float*)d_out;

    float *q, *k, *v, *att;
    __nv_bfloat16 *xh, *xl, *ah, *al, *wh, *wl;
    cudaGetSymbolAddress((void**)&q,   g_q);
    cudaGetSymbolAddress((void**)&k,   g_k);
    cudaGetSymbolAddress((void**)&v,   g_v);
    cudaGetSymbolAddress((void**)&att, g_att);
    cudaGetSymbolAddress((void**)&xh,  g_xh);
    cudaGetSymbolAddress((void**)&xl,  g_xl);
    cudaGetSymbolAddress((void**)&ah,  g_ah);
    cudaGetSymbolAddress((void**)&al,  g_al);
    cudaGetSymbolAddress((void**)&wh,  g_wh);
    cudaGetSymbolAddress((void**)&wl,  g_wl);

    cudaFuncSetAttribute(gemm_bf, cudaFuncAttributeMaxDynamicSharedMemorySize,
                         GEMM_SMEM);

    const size_t WSZ = (size_t)EDIM * EDIM;
    const int n4 = MROWS * EDIM / 4;

    conv_split<<<(n4 + 255) / 256, 256>>>((const float4*)x, (uint2*)xh, (uint2*)xl, n4);
    wtrans<<<dim3(EDIM / 32, EDIM / 32, 4), 256>>>(Wq, Wk, Wv, Wo, wh, wl);

    dim3 gemmGrid(EDIM / 128, MROWS / 256);   // (8, 16) = 128 CTAs
    gemm_bf<<<gemmGrid, 256, GEMM_SMEM>>>(xh, xl, wh,           wl,           nullptr, q);
    gemm_bf<<<gemmGrid, 256, GEMM_SMEM>>>(xh, xl, wh + WSZ,     wl + WSZ,     nullptr, k);
    gemm_bf<<<gemmGrid, 256, GEMM_SMEM>>>(xh, xl, wh + 2 * WSZ, wl + 2 * WSZ, nullptr, v);

    int nrows = MROWS * HEADS;                // 65536 rows of 64
    dim3 lnGrid(nrows * 32 / 256, 2);
    head_layernorm2<<<lnGrid, 256>>>(q, k, qln_w, qln_b, kln_w, kln_b, nrows);

    dim3 attGrid(TLEN / 64, HEADS, BATCH);    // (32, 16, 2)
    flash_attn<<<attGrid, 256>>>(q, k, v, att);

    conv_split<<<(n4 + 255) / 256, 256>>>((const float4*)att, (uint2*)ah, (uint2*)al, n4);
    gemm_bf<<<gemmGrid, 256, GEMM_SMEM>>>(ah, al, wh + 3 * WSZ, wl + 3 * WSZ, bo, out);
}

// round 6
// speedup vs baseline: 4.3158x; 3.0369x over previous
#include <cuda_runtime.h>
#include <cuda_bf16.h>
#include <math.h>
#include <stdint.h>

#define HEADS 16
#define HDIM  64
#define BATCH 2
#define TLEN  2048
#define EDIM  1024
#define MROWS (BATCH*TLEN)   // 4096

// ---------------------------------------------------------------------------
// Scratch (allocation-free rule: __device__ globals)
// ---------------------------------------------------------------------------
__device__ float g_q[MROWS*EDIM];
__device__ float g_k[MROWS*EDIM];
__device__ float g_v[MROWS*EDIM];
__device__ float g_att[MROWS*EDIM];
__device__ __align__(16) __nv_bfloat16 g_xh[MROWS*EDIM], g_xl[MROWS*EDIM];
__device__ __align__(16) __nv_bfloat16 g_ah[MROWS*EDIM], g_al[MROWS*EDIM];
__device__ __align__(16) __nv_bfloat16 g_wh[4*EDIM*EDIM], g_wl[4*EDIM*EDIM];
__device__ __align__(16) __nv_bfloat16 g_qh[MROWS*EDIM], g_ql[MROWS*EDIM];
__device__ __align__(16) __nv_bfloat16 g_kh[MROWS*EDIM], g_kl[MROWS*EDIM];
__device__ __align__(16) __nv_bfloat16 g_vth[MROWS*EDIM], g_vtl[MROWS*EDIM];

// ---------------------------------------------------------------------------
// helpers
// ---------------------------------------------------------------------------
__device__ __forceinline__ uint32_t smem_to_u32(const void* p) {
    uint32_t a;
    asm("{ .reg .u64 t; cvta.to.shared.u64 t, %1; cvt.u32.u64 %0, t; }"
        : "=r"(a) : "l"(p));
    return a;
}
__device__ __forceinline__ void cp16(uint32_t smem, const void* g) {
    asm volatile("cp.async.cg.shared.global [%0], [%1], 16;\n"
                 :: "r"(smem), "l"(g));
}
#define CP_COMMIT() asm volatile("cp.async.commit_group;\n" ::: "memory")
#define CP_WAIT(N)  asm volatile("cp.async.wait_group %0;\n" :: "n"(N) : "memory")

__device__ __forceinline__ void bsplit(float v, __nv_bfloat16& h, __nv_bfloat16& l) {
    h = __float2bfloat16_rn(v);
    l = __float2bfloat16_rn(v - __bfloat162float(h));
}
__device__ __forceinline__ unsigned pk2(__nv_bfloat16 a, __nv_bfloat16 b) {
    __nv_bfloat162 t; t.x = a; t.y = b;
    return *reinterpret_cast<unsigned*>(&t);
}
__device__ __forceinline__ unsigned pksplit_hi(float a, float b) {
    return pk2(__float2bfloat16_rn(a), __float2bfloat16_rn(b));
}
__device__ __forceinline__ void mma16(float* c, const unsigned* a, const unsigned* b) {
    asm volatile(
        "mma.sync.aligned.m16n8k16.row.col.f32.bf16.bf16.f32 "
        "{%0,%1,%2,%3}, {%4,%5,%6,%7}, {%8,%9}, {%0,%1,%2,%3};\n"
        : "+f"(c[0]), "+f"(c[1]), "+f"(c[2]), "+f"(c[3])
        : "r"(a[0]), "r"(a[1]), "r"(a[2]), "r"(a[3]), "r"(b[0]), "r"(b[1]));
}

// ---------------------------------------------------------------------------
// fp32 -> bf16 hi/lo split (elementwise, float4 vectorized)
// ---------------------------------------------------------------------------
__global__ __launch_bounds__(256)
void conv_split(const float4* __restrict__ in, uint2* __restrict__ oh,
                uint2* __restrict__ ol, int n4)
{
    int i = blockIdx.x * blockDim.x + threadIdx.x;
    if (i >= n4) return;
    float4 v = in[i];
    __nv_bfloat16 h0, l0, h1, l1, h2, l2, h3, l3;
    bsplit(v.x, h0, l0); bsplit(v.y, h1, l1);
    bsplit(v.z, h2, l2); bsplit(v.w, h3, l3);
    oh[i] = make_uint2(pk2(h0, h1), pk2(h2, h3));
    ol[i] = make_uint2(pk2(l0, l1), pk2(l2, l3));
}

// ---------------------------------------------------------------------------
// Weight transpose + bf16 hi/lo split: Wt[n][k] = W[k][n], 4 weights (grid.z)
// ---------------------------------------------------------------------------
__global__ __launch_bounds__(256)
void wtrans(const float* __restrict__ W0, const float* __restrict__ W1,
            const float* __restrict__ W2, const float* __restrict__ W3,
            __nv_bfloat16* __restrict__ oh, __nv_bfloat16* __restrict__ ol)
{
    __shared__ float tile[32][33];
    int wsel = blockIdx.z;
    const float* W = wsel == 0 ? W0 : wsel == 1 ? W1 : wsel == 2 ? W2 : W3;
    size_t obase = (size_t)wsel * EDIM * EDIM;
    int n0 = blockIdx.x * 32, k0 = blockIdx.y * 32;
    int tx = threadIdx.x & 31, ty = threadIdx.x >> 5;   // (32 x 8)
    #pragma unroll
    for (int j = 0; j < 4; j++)
        tile[ty + j * 8][tx] = W[(size_t)(k0 + ty + j * 8) * EDIM + n0 + tx];
    __syncthreads();
    #pragma unroll
    for (int j = 0; j < 4; j++) {
        float v = tile[tx][ty + j * 8];
        __nv_bfloat16 h, l;
        bsplit(v, h, l);
        size_t o = obase + (size_t)(n0 + ty + j * 8) * EDIM + k0 + tx;
        oh[o] = h; ol[o] = l;
    }
}

// ---------------------------------------------------------------------------
// V transpose per (b,h): vt[b][h][d][t] = v[b][t][h*64+d], bf16 hi/lo
// ---------------------------------------------------------------------------
__global__ __launch_bounds__(256)
void vtrans(const float* __restrict__ V,
            __nv_bfloat16* __restrict__ oh, __nv_bfloat16* __restrict__ ol)
{
    __shared__ float tile[32][33];
    int bh = blockIdx.z;             // b*16 + h
    int bb = bh >> 4, h = bh & 15;
    int t0 = blockIdx.x * 32, d0 = blockIdx.y * 32;
    int tx = threadIdx.x & 31, ty = threadIdx.x >> 5;
    #pragma unroll
    for (int j = 0; j < 4; j++)
        tile[ty + j * 8][tx] =
            V[(size_t)(bb * TLEN + t0 + ty + j * 8) * EDIM + h * HDIM + d0 + tx];
    __syncthreads();
    #pragma unroll
    for (int j = 0; j < 4; j++) {
        float v = tile[tx][ty + j * 8];
        __nv_bfloat16 hh, ll;
        bsplit(v, hh, ll);
        size_t o = ((size_t)(bh * HDIM + d0 + ty + j * 8)) * TLEN + t0 + tx;
        oh[o] = hh; ol[o] = ll;
    }
}

// ---------------------------------------------------------------------------
// bf16x3 GEMM (legacy mma, cp.async): C[M,1024] = A @ Wt^T (+ bias)
// ---------------------------------------------------------------------------
#define RS      80
#define OFF_AL  (256*RS)
#define OFF_BH  (2*256*RS)
#define OFF_BL  (2*256*RS+128*RS)
#define STAGE_B (2*256*RS+2*128*RS)
#define GEMM_SMEM (2*STAGE_B)
#define NKC     (EDIM/32)

__global__ __launch_bounds__(256, 1)
void gemm_bf(const __nv_bfloat16* __restrict__ Ah, const __nv_bfloat16* __restrict__ Al,
             const __nv_bfloat16* __restrict__ Bh, const __nv_bfloat16* __restrict__ Bl,
             const float* __restrict__ bias, float* __restrict__ C)
{
    extern __shared__ char sm[];
    const uint32_t smu = smem_to_u32(sm);

    const int tid  = threadIdx.x;
    const int lane = tid & 31;
    const int w    = tid >> 5;
    const int gid  = lane >> 2;
    const int tg   = lane & 3;
    const int warpM = (w & 3) * 64;
    const int warpN = (w >> 2) * 64;

    const int brow = blockIdx.y * 256;
    const int bcol = blockIdx.x * 128;

    const int lr = tid >> 2;
    const int lc = tid & 3;

    auto load_stage = [&](int s, int chunk) {
        uint32_t sb = smu + s * STAGE_B;
        int kel = chunk * 32 + lc * 8;
        #pragma unroll
        for (int i = 0; i < 4; i++) {
            int row = lr + 64 * i;
            size_t gi = (size_t)(brow + row) * EDIM + kel;
            uint32_t so = (uint32_t)(row * RS + lc * 16);
            cp16(sb + so,          Ah + gi);
            cp16(sb + OFF_AL + so, Al + gi);
        }
        #pragma unroll
        for (int i = 0; i < 2; i++) {
            int row = lr + 64 * i;
            size_t gi = (size_t)(bcol + row) * EDIM + kel;
            uint32_t so = (uint32_t)(row * RS + lc * 16);
            cp16(sb + OFF_BH + so, Bh + gi);
            cp16(sb + OFF_BL + so, Bl + gi);
        }
        CP_COMMIT();
    };

    float acc[4][8][4];
    #pragma unroll
    for (int mt = 0; mt < 4; mt++)
        #pragma unroll
        for (int nt = 0; nt < 8; nt++)
            #pragma unroll
            for (int i = 0; i < 4; i++) acc[mt][nt][i] = 0.f;

    load_stage(0, 0);

    for (int c = 0; c < NKC; c++) {
        int s = c & 1;
        if (c + 1 < NKC) {
            load_stage(s ^ 1, c + 1);
            CP_WAIT(1);
        } else {
            CP_WAIT(0);
        }
        __syncthreads();

        const char* base = sm + s * STAGE_B;
        #pragma unroll
        for (int ks = 0; ks < 2; ks++) {
            int koff = ks * 32 + tg * 4;
            unsigned bh[8][2], bl[8][2];
            #pragma unroll
            for (int nt = 0; nt < 8; nt++) {
                int n = warpN + nt * 8 + gid;
                const char* ph = base + OFF_BH + n * RS + koff;
                const char* pl = base + OFF_BL + n * RS + koff;
                bh[nt][0] = *(const uint32_t*)(ph);
                bh[nt][1] = *(const uint32_t*)(ph + 16);
                bl[nt][0] = *(const uint32_t*)(pl);
                bl[nt][1] = *(const uint32_t*)(pl + 16);
            }
            #pragma unroll
            for (int mt = 0; mt < 4; mt++) {
                int r = warpM + mt * 16 + gid;
                const char* pa = base + r * RS + koff;
                const char* pb = base + OFF_AL + r * RS + koff;
                unsigned ah[4], al[4];
                ah[0] = *(const uint32_t*)(pa);
                ah[1] = *(const uint32_t*)(pa + 8 * RS);
                ah[2] = *(const uint32_t*)(pa + 16);
                ah[3] = *(const uint32_t*)(pa + 8 * RS + 16);
                al[0] = *(const uint32_t*)(pb);
                al[1] = *(const uint32_t*)(pb + 8 * RS);
                al[2] = *(const uint32_t*)(pb + 16);
                al[3] = *(const uint32_t*)(pb + 8 * RS + 16);
                #pragma unroll
                for (int nt = 0; nt < 8; nt++) {
                    mma16(acc[mt][nt], ah, bl[nt]);
                    mma16(acc[mt][nt], al, bh[nt]);
                    mma16(acc[mt][nt], ah, bh[nt]);
                }
            }
        }
        __syncthreads();
    }

    #pragma unroll
    for (int mt = 0; mt < 4; mt++) {
        int r0 = brow + warpM + mt * 16 + gid;
        #pragma unroll
        for (int nt = 0; nt < 8; nt++) {
            int c0 = bcol + warpN + nt * 8 + tg * 2;
            float bx = 0.f, by = 0.f;
            if (bias) { bx = bias[c0]; by = bias[c0 + 1]; }
            *(float2*)(&C[(size_t)r0 * EDIM + c0]) =
                make_float2(acc[mt][nt][0] + bx, acc[mt][nt][1] + by);
            *(float2*)(&C[(size_t)(r0 + 8) * EDIM + c0]) =
                make_float2(acc[mt][nt][2] + bx, acc[mt][nt][3] + by);
        }
    }
}

// ---------------------------------------------------------------------------
// Per-head LayerNorm (dim 64) on q & k, emitting bf16 hi/lo directly.
// ---------------------------------------------------------------------------
__global__ __launch_bounds__(256)
void ln_bf(const float* __restrict__ q, const float* __restrict__ k,
           const float* __restrict__ qw, const float* __restrict__ qb,
           const float* __restrict__ kw, const float* __restrict__ kb,
           __nv_bfloat16* __restrict__ qh, __nv_bfloat16* __restrict__ ql,
           __nv_bfloat16* __restrict__ kh, __nv_bfloat16* __restrict__ kl,
           int nrows)
{
    const float* x = blockIdx.y ? k  : q;
    const float* w = blockIdx.y ? kw : qw;
    const float* b = blockIdx.y ? kb : qb;
    __nv_bfloat16* oh = blockIdx.y ? kh : qh;
    __nv_bfloat16* ol = blockIdx.y ? kl : ql;

    int warp = (blockIdx.x * blockDim.x + threadIdx.x) >> 5;
    int lane = threadIdx.x & 31;
    if (warp >= nrows) return;
    const float* row = x + (size_t)warp * HDIM;
    float v0 = row[lane];
    float v1 = row[lane + 32];
    float s = v0 + v1;
    #pragma unroll
    for (int o = 16; o > 0; o >>= 1) s += __shfl_xor_sync(0xffffffffu, s, o);
    float mu = s * (1.f / 64.f);
    float d0 = v0 - mu, d1 = v1 - mu;
    float vs = d0 * d0 + d1 * d1;
    #pragma unroll
    for (int o = 16; o > 0; o >>= 1) vs += __shfl_xor_sync(0xffffffffu, vs, o);
    float inv = rsqrtf(vs * (1.f / 64.f) + 1e-5f);
    float r0 = d0 * inv * w[lane]      + b[lane];
    float r1 = d1 * inv * w[lane + 32] + b[lane + 32];
    __nv_bfloat16 h0, l0, h1, l1;
    bsplit(r0, h0, l0);
    bsplit(r1, h1, l1);
    size_t base = (size_t)warp * HDIM + lane;
    oh[base] = h0; oh[base + 32] = h1;
    ol[base] = l0; ol[base + 32] = l1;
}

// ---------------------------------------------------------------------------
// Tensor-core causal flash attention (bf16x3 everywhere).
// Block: 128 q rows x one (b,h). 8 warps x 16 rows. KV tiles of 64.
// K smem [kv][d] rows 144B; V smem [d][kv] rows 144B. P passes in registers.
// ---------------------------------------------------------------------------
#define FSTR   144
#define FTILE  (64*FSTR)           // 9216
#define F_KH   0
#define F_KL   FTILE
#define F_VH   (2*FTILE)
#define F_VL   (3*FTILE)
#define FSTAGE (4*FTILE)           // 36864
#define FLASH_SMEM (2*FSTAGE)      // 73728

__global__ __launch_bounds__(256, 1)
void flash_bf(const __nv_bfloat16* __restrict__ Qh, const __nv_bfloat16* __restrict__ Ql,
              const __nv_bfloat16* __restrict__ Kh, const __nv_bfloat16* __restrict__ Kl,
              const __nv_bfloat16* __restrict__ Vth, const __nv_bfloat16* __restrict__ Vtl,
              float* __restrict__ O)
{
    extern __shared__ char sm[];
    const uint32_t smu = smem_to_u32(sm);

    const int qt = gridDim.x - 1 - blockIdx.x;   // heavy CTAs first
    const int h  = blockIdx.y;
    const int bb = blockIdx.z;
    const int tid = threadIdx.x, lane = tid & 31, w = tid >> 5;
    const int gid = lane >> 2, tg = lane & 3;
    const int q0 = qt * 128;
    const int row0 = q0 + w * 16 + gid;          // q row (within batch)

    // --- Q fragments (registers, loaded once) ---
    unsigned qfh[4][4], qfl[4][4];
    {
        size_t base = ((size_t)(bb * TLEN) + row0) * EDIM + h * HDIM;
        #pragma unroll
        for (int kt = 0; kt < 4; kt++) {
            int c = kt * 16 + tg * 2;
            qfh[kt][0] = *(const uint32_t*)(Qh + base + c);
            qfh[kt][1] = *(const uint32_t*)(Qh + base + 8 * EDIM + c);
            qfh[kt][2] = *(const uint32_t*)(Qh + base + c + 8);
            qfh[kt][3] = *(const uint32_t*)(Qh + base + 8 * EDIM + c + 8);
            qfl[kt][0] = *(const uint32_t*)(Ql + base + c);
            qfl[kt][1] = *(const uint32_t*)(Ql + base + 8 * EDIM + c);
            qfl[kt][2] = *(const uint32_t*)(Ql + base + c + 8);
            qfl[kt][3] = *(const uint32_t*)(Ql + base + 8 * EDIM + c + 8);
        }
    }

    // smem load mapping: 64 rows x 128B, 4 arrays, 8 cp16/thread
    const int lr = tid >> 2;        // 0..63
    const int lc = tid & 3;         // 0..3
    auto load_stage = [&](int s, int kv0) {
        uint32_t sb = smu + s * FSTAGE;
        uint32_t so = (uint32_t)(lr * FSTR + lc * 32);
        size_t gk = ((size_t)(bb * TLEN) + kv0 + lr) * EDIM + h * HDIM + lc * 16;
        cp16(sb + F_KH + so,      Kh + gk);
        cp16(sb + F_KH + so + 16, Kh + gk + 8);
        cp16(sb + F_KL + so,      Kl + gk);
        cp16(sb + F_KL + so + 16, Kl + gk + 8);
        size_t gv = ((size_t)((bb * HEADS + h) * HDIM + lr)) * TLEN + kv0 + lc * 16;
        cp16(sb + F_VH + so,      Vth + gv);
        cp16(sb + F_VH + so + 16, Vth + gv + 8);
        cp16(sb + F_VL + so,      Vtl + gv);
        cp16(sb + F_VL + so + 16, Vtl + gv + 8);
        CP_COMMIT();
    };

    float o[8][4];
    #pragma unroll
    for (int nt = 0; nt < 8; nt++)
        #pragma unroll
        for (int i = 0; i < 4; i++) o[nt][i] = 0.f;
    float m0 = -INFINITY, m1 = -INFINITY, l0 = 0.f, l1 = 0.f;

    const int nkv = 2 * qt + 2;
    load_stage(0, 0);

    for (int t = 0; t < nkv; t++) {
        int s = t & 1;
        if (t + 1 < nkv) {
            load_stage(s ^ 1, (t + 1) * 64);
            CP_WAIT(1);
        } else {
            CP_WAIT(0);
        }
        __syncthreads();

        int kv0 = t * 64;
        if (kv0 <= q0 + w * 16 + 15) {    // warp-uniform skip of fully-masked tiles
            const char* base = sm + s * FSTAGE;

            // ---- S = Q K^T (bf16x3) ----
            float sc[8][4];
            #pragma unroll
            for (int nt = 0; nt < 8; nt++)
                #pragma unroll
                for (int i = 0; i < 4; i++) sc[nt][i] = 0.f;

            #pragma unroll
            for (int kt = 0; kt < 4; kt++) {
                int koff = kt * 32 + tg * 4;
                #pragma unroll
                for (int nt = 0; nt < 8; nt++) {
                    int n = nt * 8 + gid;
                    const char* ph = base + F_KH + n * FSTR + koff;
                    const char* pl = base + F_KL + n * FSTR + koff;
                    unsigned bh[2], bl[2];
                    bh[0] = *(const uint32_t*)(ph);
                    bh[1] = *(const uint32_t*)(ph + 16);
                    bl[0] = *(const uint32_t*)(pl);
                    bl[1] = *(const uint32_t*)(pl + 16);
                    mma16(sc[nt], qfh[kt], bl);
                    mma16(sc[nt], qfl[kt], bh);
                    mma16(sc[nt], qfh[kt], bh);
                }
            }

            // ---- scale + causal mask ----
            #pragma unroll
            for (int nt = 0; nt < 8; nt++)
                #pragma unroll
                for (int i = 0; i < 4; i++) sc[nt][i] *= 0.125f;
            if (kv0 + 63 > row0) {
                #pragma unroll
                for (int nt = 0; nt < 8; nt++) {
                    int col = kv0 + nt * 8 + tg * 2;
                    if (col > row0)         sc[nt][0] = -INFINITY;
                    if (col + 1 > row0)     sc[nt][1] = -INFINITY;
                    if (col > row0 + 8)     sc[nt][2] = -INFINITY;
                    if (col + 1 > row0 + 8) sc[nt][3] = -INFINITY;
                }
            }

            // ---- online softmax ----
            float mx0 = -INFINITY, mx1 = -INFINITY;
            #pragma unroll
            for (int nt = 0; nt < 8; nt++) {
                mx0 = fmaxf(mx0, fmaxf(sc[nt][0], sc[nt][1]));
                mx1 = fmaxf(mx1, fmaxf(sc[nt][2], sc[nt][3]));
            }
            mx0 = fmaxf(mx0, __shfl_xor_sync(0xffffffffu, mx0, 1));
            mx0 = fmaxf(mx0, __shfl_xor_sync(0xffffffffu, mx0, 2));
            mx1 = fmaxf(mx1, __shfl_xor_sync(0xffffffffu, mx1, 1));
            mx1 = fmaxf(mx1, __shfl_xor_sync(0xffffffffu, mx1, 2));
            float mn0 = fmaxf(m0, mx0), mn1 = fmaxf(m1, mx1);
            float corr0 = __expf(m0 - mn0), corr1 = __expf(m1 - mn1);

            unsigned pfh[4][4], pfl[4][4];
            float la0 = 0.f, la1 = 0.f;
            #pragma unroll
            for (int kt = 0; kt < 4; kt++) {
                float p00 = __expf(sc[2*kt][0]   - mn0);
                float p01 = __expf(sc[2*kt][1]   - mn0);
                float p10 = __expf(sc[2*kt][2]   - mn1);
                float p11 = __expf(sc[2*kt][3]   - mn1);
                float q00 = __expf(sc[2*kt+1][0] - mn0);
                float q01 = __expf(sc[2*kt+1][1] - mn0);
                float q10 = __expf(sc[2*kt+1][2] - mn1);
                float q11 = __expf(sc[2*kt+1][3] - mn1);
                la0 += p00 + p01 + q00 + q01;
                la1 += p10 + p11 + q10 + q11;
                __nv_bfloat16 hh, ll;
                __nv_bfloat16 h2, l2;
                bsplit(p00, hh, ll); bsplit(p01, h2, l2);
                pfh[kt][0] = pk2(hh, h2); pfl[kt][0] = pk2(ll, l2);
                bsplit(p10, hh, ll); bsplit(p11, h2, l2);
                pfh[kt][1] = pk2(hh, h2); pfl[kt][1] = pk2(ll, l2);
                bsplit(q00, hh, ll); bsplit(q01, h2, l2);
                pfh[kt][2] = pk2(hh, h2); pfl[kt][2] = pk2(ll, l2);
                bsplit(q10, hh, ll); bsplit(q11, h2, l2);
                pfh[kt][3] = pk2(hh, h2); pfl[kt][3] = pk2(ll, l2);
            }
            la0 += __shfl_xor_sync(0xffffffffu, la0, 1);
            la0 += __shfl_xor_sync(0xffffffffu, la0, 2);
            la1 += __shfl_xor_sync(0xffffffffu, la1, 1);
            la1 += __shfl_xor_sync(0xffffffffu, la1, 2);
            l0 = l0 * corr0 + la0;
            l1 = l1 * corr1 + la1;
            m0 = mn0; m1 = mn1;

            #pragma unroll
            for (int nt = 0; nt < 8; nt++) {
                o[nt][0] *= corr0; o[nt][1] *= corr0;
                o[nt][2] *= corr1; o[nt][3] *= corr1;
            }

            // ---- O += P V (bf16x3) ----
            #pragma unroll
            for (int kt = 0; kt < 4; kt++) {
                int koff = kt * 32 + tg * 4;
                #pragma unroll
                for (int nt = 0; nt < 8; nt++) {
                    int n = nt * 8 + gid;
                    const char* ph = base + F_VH + n * FSTR + koff;
                    const char* pl = base + F_VL + n * FSTR + koff;
                    unsigned bh[2], bl[2];
                    bh[0] = *(const uint32_t*)(ph);
                    bh[1] = *(const uint32_t*)(ph + 16);
                    bl[0] = *(const uint32_t*)(pl);
                    bl[1] = *(const uint32_t*)(pl + 16);
                    mma16(o[nt], pfh[kt], bl);
                    mma16(o[nt], pfl[kt], bh);
                    mma16(o[nt], pfh[kt], bh);
                }
            }
        }
        __syncthreads();
    }

    // ---- epilogue ----
    float inv0 = 1.f / l0, inv1 = 1.f / l1;
    size_t ob0 = ((size_t)(bb * TLEN) + row0) * EDIM + h * HDIM;
    #pragma unroll
    for (int nt = 0; nt < 8; nt++) {
        int c = nt * 8 + tg * 2;
        *(float2*)(&O[ob0 + c]) = make_float2(o[nt][0] * inv0, o[nt][1] * inv0);
        *(float2*)(&O[ob0 + 8 * EDIM + c]) = make_float2(o[nt][2] * inv1, o[nt][3] * inv1);
    }
}

// ---------------------------------------------------------------------------
// Launch
// ---------------------------------------------------------------------------
extern "C" void kernel_launch(void* const* d_in, const int* in_sizes, int n_in,
                              void* d_out, int out_size)
{
    const float* x     = (const float*)d_in[0];
    const float* Wk    = (const float*)d_in[1];
    const float* Wq    = (const float*)d_in[2];
    const float* Wv    = (const float*)d_in[3];
    const float* Wo    = (const float*)d_in[4];
    const float* bo    = (const float*)d_in[5];
    const float* kln_w = (const float*)d_in[6];
    const float* kln_b = (const float*)d_in[7];
    const float* qln_w = (const float*)d_in[8];
    const float* qln_b = (const float*)d_in[9];
    float* out = (float*)d_out;

    float *q, *k, *v, *att;
    __nv_bfloat16 *xh, *xl, *ah, *al, *wh, *wl;
    __nv_bfloat16 *qh, *ql, *kh, *kl, *vth, *vtl;
    cudaGetSymbolAddress((void**)&q,   g_q);
    cudaGetSymbolAddress((void**)&k,   g_k);
    cudaGetSymbolAddress((void**)&v,   g_v);
    cudaGetSymbolAddress((void**)&att, g_att);
    cudaGetSymbolAddress((void**)&xh,  g_xh);
    cudaGetSymbolAddress((void**)&xl,  g_xl);
    cudaGetSymbolAddress((void**)&ah,  g_ah);
    cudaGetSymbolAddress((void**)&al,  g_al);
    cudaGetSymbolAddress((void**)&wh,  g_wh);
    cudaGetSymbolAddress((void**)&wl,  g_wl);
    cudaGetSymbolAddress((void**)&qh,  g_qh);
    cudaGetSymbolAddress((void**)&ql,  g_ql);
    cudaGetSymbolAddress((void**)&kh,  g_kh);
    cudaGetSymbolAddress((void**)&kl,  g_kl);
    cudaGetSymbolAddress((void**)&vth, g_vth);
    cudaGetSymbolAddress((void**)&vtl, g_vtl);

    cudaFuncSetAttribute(gemm_bf, cudaFuncAttributeMaxDynamicSharedMemorySize,
                         GEMM_SMEM);
    cudaFuncSetAttribute(flash_bf, cudaFuncAttributeMaxDynamicSharedMemorySize,
                         FLASH_SMEM);

    const size_t WSZ = (size_t)EDIM * EDIM;
    const int n4 = MROWS * EDIM / 4;

    conv_split<<<(n4 + 255) / 256, 256>>>((const float4*)x, (uint2*)xh, (uint2*)xl, n4);
    wtrans<<<dim3(EDIM / 32, EDIM / 32, 4), 256>>>(Wq, Wk, Wv, Wo, wh, wl);

    dim3 gemmGrid(EDIM / 128, MROWS / 256);   // (8, 16)
    gemm_bf<<<gemmGrid, 256, GEMM_SMEM>>>(xh, xl, wh,           wl,           nullptr, q);
    gemm_bf<<<gemmGrid, 256, GEMM_SMEM>>>(xh, xl, wh + WSZ,     wl + WSZ,     nullptr, k);
    gemm_bf<<<gemmGrid, 256, GEMM_SMEM>>>(xh, xl, wh + 2 * WSZ, wl + 2 * WSZ, nullptr, v);

    int nrows = MROWS * HEADS;                // 65536
    dim3 lnGrid(nrows * 32 / 256, 2);
    ln_bf<<<lnGrid, 256>>>(q, k, qln_w, qln_b, kln_w, kln_b, qh, ql, kh, kl, nrows);

    vtrans<<<dim3(TLEN / 32, HDIM / 32, BATCH * HEADS), 256>>>(v, vth, vtl);

    dim3 fGrid(TLEN / 128, HEADS, BATCH);     // (16, 16, 2) = 512 CTAs
    flash_bf<<<fGrid, 256, FLASH_SMEM>>>(qh, ql, kh, kl, vth, vtl, att);

    conv_split<<<(n4 + 255) / 256, 256>>>((const float4*)att, (uint2*)ah, (uint2*)al, n4);
    gemm_bf<<<gemmGrid, 256, GEMM_SMEM>>>(ah, al, wh + 3 * WSZ, wl + 3 * WSZ, bo, out);
}

// round 7
// speedup vs baseline: 5.8749x; 1.3613x over previous
#include <cuda_runtime.h>
#include <cuda_fp16.h>
#include <math.h>
#include <stdint.h>

#define HEADS 16
#define HDIM  64
#define BATCH 2
#define TLEN  2048
#define EDIM  1024
#define MROWS (BATCH*TLEN)   // 4096

// ---------------------------------------------------------------------------
// Scratch (allocation-free rule: __device__ globals)
// ---------------------------------------------------------------------------
__device__ float g_q[MROWS*EDIM];
__device__ float g_k[MROWS*EDIM];
__device__ float g_v[MROWS*EDIM];
__device__ __align__(16) __half g_xh[MROWS*EDIM], g_xl[MROWS*EDIM];
__device__ __align__(16) __half g_ah[MROWS*EDIM], g_al[MROWS*EDIM];
__device__ __align__(16) __half g_wh[4*EDIM*EDIM];
__device__ __align__(16) __half g_qh[MROWS*EDIM], g_ql[MROWS*EDIM];
__device__ __align__(16) __half g_kh[MROWS*EDIM];
__device__ __align__(16) __half g_vth[MROWS*EDIM];

// ---------------------------------------------------------------------------
// helpers
// ---------------------------------------------------------------------------
__device__ __forceinline__ uint32_t smem_to_u32(const void* p) {
    uint32_t a;
    asm("{ .reg .u64 t; cvta.to.shared.u64 t, %1; cvt.u32.u64 %0, t; }"
        : "=r"(a) : "l"(p));
    return a;
}
__device__ __forceinline__ void cp16(uint32_t smem, const void* g) {
    asm volatile("cp.async.cg.shared.global [%0], [%1], 16;\n"
                 :: "r"(smem), "l"(g));
}
#define CP_COMMIT() asm volatile("cp.async.commit_group;\n" ::: "memory")
#define CP_WAIT(N)  asm volatile("cp.async.wait_group %0;\n" :: "n"(N) : "memory")

__device__ __forceinline__ void hsplit(float v, __half& h, __half& l) {
    h = __float2half_rn(v);
    l = __float2half_rn(v - __half2float(h));
}
__device__ __forceinline__ unsigned pkh(__half a, __half b) {
    __half2 t; t.x = a; t.y = b;
    return *reinterpret_cast<unsigned*>(&t);
}
__device__ __forceinline__ void mma16(float* c, const unsigned* a, const unsigned* b) {
    asm volatile(
        "mma.sync.aligned.m16n8k16.row.col.f32.f16.f16.f32 "
        "{%0,%1,%2,%3}, {%4,%5,%6,%7}, {%8,%9}, {%0,%1,%2,%3};\n"
        : "+f"(c[0]), "+f"(c[1]), "+f"(c[2]), "+f"(c[3])
        : "r"(a[0]), "r"(a[1]), "r"(a[2]), "r"(a[3]), "r"(b[0]), "r"(b[1]));
}

// ---------------------------------------------------------------------------
// fp32 -> fp16 hi/lo split (elementwise, float4 vectorized)
// ---------------------------------------------------------------------------
__global__ __launch_bounds__(256)
void conv_split(const float4* __restrict__ in, uint2* __restrict__ oh,
                uint2* __restrict__ ol, int n4)
{
    int i = blockIdx.x * blockDim.x + threadIdx.x;
    if (i >= n4) return;
    float4 v = in[i];
    __half h0, l0, h1, l1, h2, l2, h3, l3;
    hsplit(v.x, h0, l0); hsplit(v.y, h1, l1);
    hsplit(v.z, h2, l2); hsplit(v.w, h3, l3);
    oh[i] = make_uint2(pkh(h0, h1), pkh(h2, h3));
    ol[i] = make_uint2(pkh(l0, l1), pkh(l2, l3));
}

// ---------------------------------------------------------------------------
// Weight transpose + fp16 round: Wt[n][k] = fp16(W[k][n]), 4 weights (grid.z)
// ---------------------------------------------------------------------------
__global__ __launch_bounds__(256)
void wtrans(const float* __restrict__ W0, const float* __restrict__ W1,
            const float* __restrict__ W2, const float* __restrict__ W3,
            __half* __restrict__ oh)
{
    __shared__ float tile[32][33];
    int wsel = blockIdx.z;
    const float* W = wsel == 0 ? W0 : wsel == 1 ? W1 : wsel == 2 ? W2 : W3;
    size_t obase = (size_t)wsel * EDIM * EDIM;
    int n0 = blockIdx.x * 32, k0 = blockIdx.y * 32;
    int tx = threadIdx.x & 31, ty = threadIdx.x >> 5;   // (32 x 8)
    #pragma unroll
    for (int j = 0; j < 4; j++)
        tile[ty + j * 8][tx] = W[(size_t)(k0 + ty + j * 8) * EDIM + n0 + tx];
    __syncthreads();
    #pragma unroll
    for (int j = 0; j < 4; j++) {
        size_t o = obase + (size_t)(n0 + ty + j * 8) * EDIM + k0 + tx;
        oh[o] = __float2half_rn(tile[tx][ty + j * 8]);
    }
}

// ---------------------------------------------------------------------------
// V transpose per (b,h): vt[b][h][d][t] = fp16(v[b][t][h*64+d])
// ---------------------------------------------------------------------------
__global__ __launch_bounds__(256)
void vtrans(const float* __restrict__ V, __half* __restrict__ oh)
{
    __shared__ float tile[32][33];
    int bh = blockIdx.z;             // b*16 + h
    int bb = bh >> 4, h = bh & 15;
    int t0 = blockIdx.x * 32, d0 = blockIdx.y * 32;
    int tx = threadIdx.x & 31, ty = threadIdx.x >> 5;
    #pragma unroll
    for (int j = 0; j < 4; j++)
        tile[ty + j * 8][tx] =
            V[(size_t)(bb * TLEN + t0 + ty + j * 8) * EDIM + h * HDIM + d0 + tx];
    __syncthreads();
    #pragma unroll
    for (int j = 0; j < 4; j++) {
        size_t o = ((size_t)(bh * HDIM + d0 + ty + j * 8)) * TLEN + t0 + tx;
        oh[o] = __float2half_rn(tile[tx][ty + j * 8]);
    }
}

// ---------------------------------------------------------------------------
// fp16 2-term GEMM: C = (Ah+Al) @ Bh^T (+ bias). Block 256x128, BK=32.
// smem rows RS=80 B (conflict-free fragment pattern, proven in R5).
// ---------------------------------------------------------------------------
#define RS      80
#define OFF_AL  (256*RS)             // 20480
#define OFF_BH  (2*256*RS)           // 40960
#define STAGE_B (2*256*RS + 128*RS)  // 51200
#define GEMM_SMEM (2*STAGE_B)        // 102400
#define NKC     (EDIM/32)            // 32

__global__ __launch_bounds__(256, 1)
void gemm_h(const __half* __restrict__ Ah, const __half* __restrict__ Al,
            const __half* __restrict__ Bh,
            const float* __restrict__ bias, float* __restrict__ C)
{
    extern __shared__ char sm[];
    const uint32_t smu = smem_to_u32(sm);

    const int tid  = threadIdx.x;
    const int lane = tid & 31;
    const int w    = tid >> 5;
    const int gid  = lane >> 2;
    const int tg   = lane & 3;
    const int warpM = (w & 3) * 64;
    const int warpN = (w >> 2) * 64;

    const int brow = blockIdx.y * 256;
    const int bcol = blockIdx.x * 128;

    const int lr = tid >> 2;
    const int lc = tid & 3;

    auto load_stage = [&](int s, int chunk) {
        uint32_t sb = smu + s * STAGE_B;
        int kel = chunk * 32 + lc * 8;
        #pragma unroll
        for (int i = 0; i < 4; i++) {
            int row = lr + 64 * i;
            size_t gi = (size_t)(brow + row) * EDIM + kel;
            uint32_t so = (uint32_t)(row * RS + lc * 16);
            cp16(sb + so,          Ah + gi);
            cp16(sb + OFF_AL + so, Al + gi);
        }
        #pragma unroll
        for (int i = 0; i < 2; i++) {
            int row = lr + 64 * i;
            size_t gi = (size_t)(bcol + row) * EDIM + kel;
            uint32_t so = (uint32_t)(row * RS + lc * 16);
            cp16(sb + OFF_BH + so, Bh + gi);
        }
        CP_COMMIT();
    };

    float acc[4][8][4];
    #pragma unroll
    for (int mt = 0; mt < 4; mt++)
        #pragma unroll
        for (int nt = 0; nt < 8; nt++)
            #pragma unroll
            for (int i = 0; i < 4; i++) acc[mt][nt][i] = 0.f;

    load_stage(0, 0);

    for (int c = 0; c < NKC; c++) {
        int s = c & 1;
        if (c + 1 < NKC) {
            load_stage(s ^ 1, c + 1);
            CP_WAIT(1);
        } else {
            CP_WAIT(0);
        }
        __syncthreads();

        const char* base = sm + s * STAGE_B;
        #pragma unroll
        for (int ks = 0; ks < 2; ks++) {
            int koff = ks * 32 + tg * 4;
            unsigned bh[8][2];
            #pragma unroll
            for (int nt = 0; nt < 8; nt++) {
                int n = warpN + nt * 8 + gid;
                const char* ph = base + OFF_BH + n * RS + koff;
                bh[nt][0] = *(const uint32_t*)(ph);
                bh[nt][1] = *(const uint32_t*)(ph + 16);
            }
            #pragma unroll
            for (int mt = 0; mt < 4; mt++) {
                int r = warpM + mt * 16 + gid;
                const char* pa = base + r * RS + koff;
                const char* pb = base + OFF_AL + r * RS + koff;
                unsigned ah[4], al[4];
                ah[0] = *(const uint32_t*)(pa);
                ah[1] = *(const uint32_t*)(pa + 8 * RS);
                ah[2] = *(const uint32_t*)(pa + 16);
                ah[3] = *(const uint32_t*)(pa + 8 * RS + 16);
                al[0] = *(const uint32_t*)(pb);
                al[1] = *(const uint32_t*)(pb + 8 * RS);
                al[2] = *(const uint32_t*)(pb + 16);
                al[3] = *(const uint32_t*)(pb + 8 * RS + 16);
                #pragma unroll
                for (int nt = 0; nt < 8; nt++) {
                    mma16(acc[mt][nt], ah, bh[nt]);
                    mma16(acc[mt][nt], al, bh[nt]);
                }
            }
        }
        __syncthreads();
    }

    #pragma unroll
    for (int mt = 0; mt < 4; mt++) {
        int r0 = brow + warpM + mt * 16 + gid;
        #pragma unroll
        for (int nt = 0; nt < 8; nt++) {
            int c0 = bcol + warpN + nt * 8 + tg * 2;
            float bx = 0.f, by = 0.f;
            if (bias) { bx = bias[c0]; by = bias[c0 + 1]; }
            *(float2*)(&C[(size_t)r0 * EDIM + c0]) =
                make_float2(acc[mt][nt][0] + bx, acc[mt][nt][1] + by);
            *(float2*)(&C[(size_t)(r0 + 8) * EDIM + c0]) =
                make_float2(acc[mt][nt][2] + bx, acc[mt][nt][3] + by);
        }
    }
}

// ---------------------------------------------------------------------------
// Per-head LayerNorm (dim 64): q -> fp16 hi/lo, k -> single fp16.
// ---------------------------------------------------------------------------
__global__ __launch_bounds__(256)
void ln_h(const float* __restrict__ q, const float* __restrict__ k,
          const float* __restrict__ qw, const float* __restrict__ qb,
          const float* __restrict__ kw, const float* __restrict__ kb,
          __half* __restrict__ qh, __half* __restrict__ ql,
          __half* __restrict__ kh, int nrows)
{
    const float* x = blockIdx.y ? k  : q;
    const float* w = blockIdx.y ? kw : qw;
    const float* b = blockIdx.y ? kb : qb;

    int warp = (blockIdx.x * blockDim.x + threadIdx.x) >> 5;
    int lane = threadIdx.x & 31;
    if (warp >= nrows) return;
    const float* row = x + (size_t)warp * HDIM;
    float v0 = row[lane];
    float v1 = row[lane + 32];
    float s = v0 + v1;
    #pragma unroll
    for (int o = 16; o > 0; o >>= 1) s += __shfl_xor_sync(0xffffffffu, s, o);
    float mu = s * (1.f / 64.f);
    float d0 = v0 - mu, d1 = v1 - mu;
    float vs = d0 * d0 + d1 * d1;
    #pragma unroll
    for (int o = 16; o > 0; o >>= 1) vs += __shfl_xor_sync(0xffffffffu, vs, o);
    float inv = rsqrtf(vs * (1.f / 64.f) + 1e-5f);
    float r0 = d0 * inv * w[lane]      + b[lane];
    float r1 = d1 * inv * w[lane + 32] + b[lane + 32];
    size_t base = (size_t)warp * HDIM + lane;
    if (blockIdx.y) {
        kh[base]      = __float2half_rn(r0);
        kh[base + 32] = __float2half_rn(r1);
    } else {
        __half h0, l0, h1, l1;
        hsplit(r0, h0, l0);
        hsplit(r1, h1, l1);
        qh[base] = h0; qh[base + 32] = h1;
        ql[base] = l0; ql[base + 32] = l1;
    }
}

// ---------------------------------------------------------------------------
// Tensor-core causal flash attention, fp16 2-term.
// Block: 128 q rows x one (b,h). 8 warps x 16 rows. KV tiles of 64.
// K smem [kv][d], V smem [d][kv], rows 144B. P in registers (hi/lo).
// Epilogue writes fp16 hi/lo of O directly (feeds final GEMM).
// ---------------------------------------------------------------------------
#define FSTR   144
#define FTILE  (64*FSTR)           // 9216
#define F_KH   0
#define F_VH   FTILE
#define FSTAGE (2*FTILE)           // 18432
#define FLASH_SMEM (2*FSTAGE)      // 36864

__global__ __launch_bounds__(256, 1)
void flash_h(const __half* __restrict__ Qh, const __half* __restrict__ Ql,
             const __half* __restrict__ Kh, const __half* __restrict__ Vth,
             __half* __restrict__ OH, __half* __restrict__ OL)
{
    extern __shared__ char sm[];
    const uint32_t smu = smem_to_u32(sm);

    const int qt = gridDim.x - 1 - blockIdx.x;   // heavy CTAs first
    const int h  = blockIdx.y;
    const int bb = blockIdx.z;
    const int tid = threadIdx.x, lane = tid & 31, w = tid >> 5;
    const int gid = lane >> 2, tg = lane & 3;
    const int q0 = qt * 128;
    const int row0 = q0 + w * 16 + gid;

    // --- Q fragments (registers, loaded once) ---
    unsigned qfh[4][4], qfl[4][4];
    {
        size_t base = ((size_t)(bb * TLEN) + row0) * EDIM + h * HDIM;
        #pragma unroll
        for (int kt = 0; kt < 4; kt++) {
            int c = kt * 16 + tg * 2;
            qfh[kt][0] = *(const uint32_t*)(Qh + base + c);
            qfh[kt][1] = *(const uint32_t*)(Qh + base + 8 * EDIM + c);
            qfh[kt][2] = *(const uint32_t*)(Qh + base + c + 8);
            qfh[kt][3] = *(const uint32_t*)(Qh + base + 8 * EDIM + c + 8);
            qfl[kt][0] = *(const uint32_t*)(Ql + base + c);
            qfl[kt][1] = *(const uint32_t*)(Ql + base + 8 * EDIM + c);
            qfl[kt][2] = *(const uint32_t*)(Ql + base + c + 8);
            qfl[kt][3] = *(const uint32_t*)(Ql + base + 8 * EDIM + c + 8);
        }
    }

    const int lr = tid >> 2;        // 0..63
    const int lc = tid & 3;         // 0..3
    auto load_stage = [&](int s, int kv0) {
        uint32_t sb = smu + s * FSTAGE;
        uint32_t so = (uint32_t)(lr * FSTR + lc * 32);
        size_t gk = ((size_t)(bb * TLEN) + kv0 + lr) * EDIM + h * HDIM + lc * 16;
        cp16(sb + F_KH + so,      Kh + gk);
        cp16(sb + F_KH + so + 16, Kh + gk + 8);
        size_t gv = ((size_t)((bb * HEADS + h) * HDIM + lr)) * TLEN + kv0 + lc * 16;
        cp16(sb + F_VH + so,      Vth + gv);
        cp16(sb + F_VH + so + 16, Vth + gv + 8);
        CP_COMMIT();
    };

    float o[8][4];
    #pragma unroll
    for (int nt = 0; nt < 8; nt++)
        #pragma unroll
        for (int i = 0; i < 4; i++) o[nt][i] = 0.f;
    float m0 = -INFINITY, m1 = -INFINITY, l0 = 0.f, l1 = 0.f;

    const int nkv = 2 * qt + 2;
    load_stage(0, 0);

    for (int t = 0; t < nkv; t++) {
        int s = t & 1;
        if (t + 1 < nkv) {
            load_stage(s ^ 1, (t + 1) * 64);
            CP_WAIT(1);
        } else {
            CP_WAIT(0);
        }
        __syncthreads();

        int kv0 = t * 64;
        if (kv0 <= q0 + w * 16 + 15) {
            const char* base = sm + s * FSTAGE;

            // ---- S = Q K^T ----
            float sc[8][4];
            #pragma unroll
            for (int nt = 0; nt < 8; nt++)
                #pragma unroll
                for (int i = 0; i < 4; i++) sc[nt][i] = 0.f;

            #pragma unroll
            for (int kt = 0; kt < 4; kt++) {
                int koff = kt * 32 + tg * 4;
                #pragma unroll
                for (int nt = 0; nt < 8; nt++) {
                    int n = nt * 8 + gid;
                    const char* ph = base + F_KH + n * FSTR + koff;
                    unsigned bh[2];
                    bh[0] = *(const uint32_t*)(ph);
                    bh[1] = *(const uint32_t*)(ph + 16);
                    mma16(sc[nt], qfh[kt], bh);
                    mma16(sc[nt], qfl[kt], bh);
                }
            }

            // ---- scale + causal mask ----
            #pragma unroll
            for (int nt = 0; nt < 8; nt++)
                #pragma unroll
                for (int i = 0; i < 4; i++) sc[nt][i] *= 0.125f;
            if (kv0 + 63 > row0) {
                #pragma unroll
                for (int nt = 0; nt < 8; nt++) {
                    int col = kv0 + nt * 8 + tg * 2;
                    if (col > row0)         sc[nt][0] = -INFINITY;
                    if (col + 1 > row0)     sc[nt][1] = -INFINITY;
                    if (col > row0 + 8)     sc[nt][2] = -INFINITY;
                    if (col + 1 > row0 + 8) sc[nt][3] = -INFINITY;
                }
            }

            // ---- online softmax ----
            float mx0 = -INFINITY, mx1 = -INFINITY;
            #pragma unroll
            for (int nt = 0; nt < 8; nt++) {
                mx0 = fmaxf(mx0, fmaxf(sc[nt][0], sc[nt][1]));
                mx1 = fmaxf(mx1, fmaxf(sc[nt][2], sc[nt][3]));
            }
            mx0 = fmaxf(mx0, __shfl_xor_sync(0xffffffffu, mx0, 1));
            mx0 = fmaxf(mx0, __shfl_xor_sync(0xffffffffu, mx0, 2));
            mx1 = fmaxf(mx1, __shfl_xor_sync(0xffffffffu, mx1, 1));
            mx1 = fmaxf(mx1, __shfl_xor_sync(0xffffffffu, mx1, 2));
            float mn0 = fmaxf(m0, mx0), mn1 = fmaxf(m1, mx1);
            float corr0 = __expf(m0 - mn0), corr1 = __expf(m1 - mn1);

            unsigned pfh[4][4], pfl[4][4];
            float la0 = 0.f, la1 = 0.f;
            #pragma unroll
            for (int kt = 0; kt < 4; kt++) {
                float p00 = __expf(sc[2*kt][0]   - mn0);
                float p01 = __expf(sc[2*kt][1]   - mn0);
                float p10 = __expf(sc[2*kt][2]   - mn1);
                float p11 = __expf(sc[2*kt][3]   - mn1);
                float q00 = __expf(sc[2*kt+1][0] - mn0);
                float q01 = __expf(sc[2*kt+1][1] - mn0);
                float q10 = __expf(sc[2*kt+1][2] - mn1);
                float q11 = __expf(sc[2*kt+1][3] - mn1);
                la0 += p00 + p01 + q00 + q01;
                la1 += p10 + p11 + q10 + q11;
                __half hh, ll, h2, l2;
                hsplit(p00, hh, ll); hsplit(p01, h2, l2);
                pfh[kt][0] = pkh(hh, h2); pfl[kt][0] = pkh(ll, l2);
                hsplit(p10, hh, ll); hsplit(p11, h2, l2);
                pfh[kt][1] = pkh(hh, h2); pfl[kt][1] = pkh(ll, l2);
                hsplit(q00, hh, ll); hsplit(q01, h2, l2);
                pfh[kt][2] = pkh(hh, h2); pfl[kt][2] = pkh(ll, l2);
                hsplit(q10, hh, ll); hsplit(q11, h2, l2);
                pfh[kt][3] = pkh(hh, h2); pfl[kt][3] = pkh(ll, l2);
            }
            la0 += __shfl_xor_sync(0xffffffffu, la0, 1);
            la0 += __shfl_xor_sync(0xffffffffu, la0, 2);
            la1 += __shfl_xor_sync(0xffffffffu, la1, 1);
            la1 += __shfl_xor_sync(0xffffffffu, la1, 2);
            l0 = l0 * corr0 + la0;
            l1 = l1 * corr1 + la1;
            m0 = mn0; m1 = mn1;

            #pragma unroll
            for (int nt = 0; nt < 8; nt++) {
                o[nt][0] *= corr0; o[nt][1] *= corr0;
                o[nt][2] *= corr1; o[nt][3] *= corr1;
            }

            // ---- O += P V ----
            #pragma unroll
            for (int kt = 0; kt < 4; kt++) {
                int koff = kt * 32 + tg * 4;
                #pragma unroll
                for (int nt = 0; nt < 8; nt++) {
                    int n = nt * 8 + gid;
                    const char* ph = base + F_VH + n * FSTR + koff;
                    unsigned bh[2];
                    bh[0] = *(const uint32_t*)(ph);
                    bh[1] = *(const uint32_t*)(ph + 16);
                    mma16(o[nt], pfh[kt], bh);
                    mma16(o[nt], pfl[kt], bh);
                }
            }
        }
        __syncthreads();
    }

    // ---- epilogue: write fp16 hi/lo of normalized O ----
    float inv0 = 1.f / l0, inv1 = 1.f / l1;
    size_t ob0 = ((size_t)(bb * TLEN) + row0) * EDIM + h * HDIM;
    #pragma unroll
    for (int nt = 0; nt < 8; nt++) {
        int c = nt * 8 + tg * 2;
        float a0 = o[nt][0] * inv0, a1 = o[nt][1] * inv0;
        float b0 = o[nt][2] * inv1, b1 = o[nt][3] * inv1;
        __half h0, L0, h1, L1;
        hsplit(a0, h0, L0); hsplit(a1, h1, L1);
        *(uint32_t*)(OH + ob0 + c) = pkh(h0, h1);
        *(uint32_t*)(OL + ob0 + c) = pkh(L0, L1);
        hsplit(b0, h0, L0); hsplit(b1, h1, L1);
        *(uint32_t*)(OH + ob0 + 8 * EDIM + c) = pkh(h0, h1);
        *(uint32_t*)(OL + ob0 + 8 * EDIM + c) = pkh(L0, L1);
    }
}

// ---------------------------------------------------------------------------
// Launch
// ---------------------------------------------------------------------------
extern "C" void kernel_launch(void* const* d_in, const int* in_sizes, int n_in,
                              void* d_out, int out_size)
{
    const float* x     = (const float*)d_in[0];
    const float* Wk    = (const float*)d_in[1];
    const float* Wq    = (const float*)d_in[2];
    const float* Wv    = (const float*)d_in[3];
    const float* Wo    = (const float*)d_in[4];
    const float* bo    = (const float*)d_in[5];
    const float* kln_w = (const float*)d_in[6];
    const float* kln_b = (const float*)d_in[7];
    const float* qln_w = (const float*)d_in[8];
    const float* qln_b = (const float*)d_in[9];
    float* out = (float*)d_out;

    float *q, *k, *v;
    __half *xh, *xl, *ah, *al, *wh, *qh, *ql, *kh, *vth;
    cudaGetSymbolAddress((void**)&q,   g_q);
    cudaGetSymbolAddress((void**)&k,   g_k);
    cudaGetSymbolAddress((void**)&v,   g_v);
    cudaGetSymbolAddress((void**)&xh,  g_xh);
    cudaGetSymbolAddress((void**)&xl,  g_xl);
    cudaGetSymbolAddress((void**)&ah,  g_ah);
    cudaGetSymbolAddress((void**)&al,  g_al);
    cudaGetSymbolAddress((void**)&wh,  g_wh);
    cudaGetSymbolAddress((void**)&qh,  g_qh);
    cudaGetSymbolAddress((void**)&ql,  g_ql);
    cudaGetSymbolAddress((void**)&kh,  g_kh);
    cudaGetSymbolAddress((void**)&vth, g_vth);

    cudaFuncSetAttribute(gemm_h, cudaFuncAttributeMaxDynamicSharedMemorySize,
                         GEMM_SMEM);
    cudaFuncSetAttribute(flash_h, cudaFuncAttributeMaxDynamicSharedMemorySize,
                         FLASH_SMEM);

    const size_t WSZ = (size_t)EDIM * EDIM;
    const int n4 = MROWS * EDIM / 4;

    conv_split<<<(n4 + 255) / 256, 256>>>((const float4*)x, (uint2*)xh, (uint2*)xl, n4);
    wtrans<<<dim3(EDIM / 32, EDIM / 32, 4), 256>>>(Wq, Wk, Wv, Wo, wh);

    dim3 gemmGrid(EDIM / 128, MROWS / 256);   // (8, 16)
    gemm_h<<<gemmGrid, 256, GEMM_SMEM>>>(xh, xl, wh,           nullptr, q);
    gemm_h<<<gemmGrid, 256, GEMM_SMEM>>>(xh, xl, wh + WSZ,     nullptr, k);
    gemm_h<<<gemmGrid, 256, GEMM_SMEM>>>(xh, xl, wh + 2 * WSZ, nullptr, v);

    int nrows = MROWS * HEADS;                // 65536
    dim3 lnGrid(nrows * 32 / 256, 2);
    ln_h<<<lnGrid, 256>>>(q, k, qln_w, qln_b, kln_w, kln_b, qh, ql, kh, nrows);

    vtrans<<<dim3(TLEN / 32, HDIM / 32, BATCH * HEADS), 256>>>(v, vth);

    dim3 fGrid(TLEN / 128, HEADS, BATCH);     // (16, 16, 2)
    flash_h<<<fGrid, 256, FLASH_SMEM>>>(qh, ql, kh, vth, ah, al);

    gemm_h<<<gemmGrid, 256, GEMM_SMEM>>>(ah, al, wh + 3 * WSZ, bo, out);
}